// round 14
// baseline (speedup 1.0000x reference)
#include <cuda_runtime.h>
#include <cuda_bf16.h>
#include <cuda_fp16.h>
#include <cstdint>
#include <math.h>

// ---------------------------------------------------------------------------
// Problem constants
// ---------------------------------------------------------------------------
constexpr int L = 4;
constexpr int C = 1024;
constexpr int F = 4096;
constexpr int V = 50304;
constexpr int B = 2;
constexpr int T = 1024;
constexpr int M = B * T;            // 2048 rows
constexpr int CH = 16;              // wkv chunks
constexpr int CL = 64;              // wkv chunk length

// ---------------------------------------------------------------------------
// Converted-weight layout: single fp16, SAME [K,N] layout as inputs.
// ---------------------------------------------------------------------------
constexpr size_t MB1 = size_t(C) * C;         // 1,048,576
constexpr size_t O_WR   = 0;                  // [L][C][C]  (Wk = +4MB1, Wv = +8MB1)
constexpr size_t O_WK   = 4 * MB1;
constexpr size_t O_WV   = 8 * MB1;
constexpr size_t O_WO   = 12 * MB1;
constexpr size_t O_WFR  = 16 * MB1;
constexpr size_t O_WFK  = 20 * MB1;           // [L][C][F]
constexpr size_t O_WFV  = 36 * MB1;           // [L][F][C]
constexpr size_t O_HEAD = 52 * MB1;           // [C][V]
constexpr size_t WTOTAL = O_HEAD + size_t(V) * C;

__device__ alignas(16) __half g_wt[WTOTAL];

__device__ alignas(16) float g_x   [size_t(M) * C];
__device__ alignas(16) float g_r   [size_t(M) * C];
__device__ alignas(16) float g_k   [size_t(M) * C];
__device__ alignas(16) float g_v   [size_t(M) * C];
__device__ alignas(16) float g_sakv[size_t(M) * C];
__device__ alignas(16) float g_sak [size_t(M) * C];
__device__ alignas(16) __half g_xn_hi[size_t(M) * C];
__device__ alignas(16) __half g_xn_lo[size_t(M) * C];
__device__ alignas(16) __half g_y_hi [size_t(M) * C];
__device__ alignas(16) __half g_y_lo [size_t(M) * C];
__device__ alignas(16) __half g_kf_hi[size_t(M) * F];
__device__ alignas(16) __half g_kf_lo[size_t(M) * F];

// wkv chunk-scan scratch: [B][CH][C]
constexpr int AGG = B * CH * C;    // 32768
__device__ alignas(16) float g_aggFkv[AGG];
__device__ alignas(16) float g_aggFk [AGG];
__device__ alignas(16) float g_aggBkv[AGG];
__device__ alignas(16) float g_aggBk [AGG];
__device__ alignas(16) float g_iniFkv[AGG];
__device__ alignas(16) float g_iniFk [AGG];
__device__ alignas(16) float g_iniBkv[AGG];
__device__ alignas(16) float g_iniBk [AGG];

// ---------------------------------------------------------------------------
// Merged streaming conversion: fp32 -> single fp16, 16B stores.
// ---------------------------------------------------------------------------
constexpr size_t N4_CC = size_t(L) * C * C / 4;
constexpr size_t N4_CF = size_t(L) * C * F / 4;
constexpr size_t N4_HD = size_t(V) * C / 4;
constexpr size_t CV_B0 = N4_CC;
constexpr size_t CV_B1 = CV_B0 + N4_CC;
constexpr size_t CV_B2 = CV_B1 + N4_CC;
constexpr size_t CV_B3 = CV_B2 + N4_CC;
constexpr size_t CV_B4 = CV_B3 + N4_CC;
constexpr size_t CV_B5 = CV_B4 + N4_CF;
constexpr size_t CV_B6 = CV_B5 + N4_CF;
constexpr size_t CV_TOT = CV_B6 + N4_HD;
constexpr size_t CV_G = CV_TOT / 2;           // groups of 2 float4 (8 floats)

__device__ __forceinline__ uint32_t pack_h2(float a, float b) {
    __half2 h;
    h.x = __float2half(a);
    h.y = __float2half(b);
    return *(uint32_t*)&h;
}

__global__ __launch_bounds__(256) void convert_all_k(
    const float4* __restrict__ wr, const float4* __restrict__ wk,
    const float4* __restrict__ wv, const float4* __restrict__ wo,
    const float4* __restrict__ wfr, const float4* __restrict__ wfk,
    const float4* __restrict__ wfv, const float4* __restrict__ hd,
    uint4* __restrict__ oh) {
    size_t stride = (size_t)gridDim.x * blockDim.x;
    for (size_t g = (size_t)blockIdx.x * blockDim.x + threadIdx.x; g < CV_G;
         g += stride) {
        size_t i = 2 * g;
        const float4* src;
        size_t dstg;   // uint4 index (8 halves)
        if (i < CV_B0)      { src = wr  + i;            dstg = O_WR  / 8 + g; }
        else if (i < CV_B1) { src = wk  + (i - CV_B0);  dstg = O_WK  / 8 + (g - CV_B0 / 2); }
        else if (i < CV_B2) { src = wv  + (i - CV_B1);  dstg = O_WV  / 8 + (g - CV_B1 / 2); }
        else if (i < CV_B3) { src = wo  + (i - CV_B2);  dstg = O_WO  / 8 + (g - CV_B2 / 2); }
        else if (i < CV_B4) { src = wfr + (i - CV_B3);  dstg = O_WFR / 8 + (g - CV_B3 / 2); }
        else if (i < CV_B5) { src = wfk + (i - CV_B4);  dstg = O_WFK / 8 + (g - CV_B4 / 2); }
        else if (i < CV_B6) { src = wfv + (i - CV_B5);  dstg = O_WFV / 8 + (g - CV_B5 / 2); }
        else                { src = hd  + (i - CV_B6);  dstg = O_HEAD/ 8 + (g - CV_B6 / 2); }
        float4 w0 = src[0];
        float4 w1 = src[1];
        uint4 H;
        H.x = pack_h2(w0.x, w0.y);
        H.y = pack_h2(w0.z, w0.w);
        H.z = pack_h2(w1.x, w1.y);
        H.w = pack_h2(w1.z, w1.w);
        oh[dstg] = H;
    }
}

// ---------------------------------------------------------------------------
// Embedding gather
// ---------------------------------------------------------------------------
__global__ void embed_k(const int* __restrict__ idx,
                        const float* __restrict__ emb,
                        float* __restrict__ x) {
    int row = blockIdx.x;
    int id = idx[row];
    const float4* src = (const float4*)(emb + (size_t)id * C);
    float4* dst = (float4*)(x + (size_t)row * C);
    for (int i = threadIdx.x; i < C / 4; i += blockDim.x) dst[i] = src[i];
}

// ---------------------------------------------------------------------------
// LayerNorm -> split fp16 output (hi + residual lo)
// ---------------------------------------------------------------------------
__global__ __launch_bounds__(256) void layernorm_k(const float* __restrict__ x,
                                                   const float* __restrict__ w,
                                                   const float* __restrict__ b,
                                                   __half* __restrict__ out_hi,
                                                   __half* __restrict__ out_lo) {
    __shared__ float red[256];
    int row = blockIdx.x;
    const float* xr = x + (size_t)row * C;
    float v[4];
    float s = 0.f;
#pragma unroll
    for (int i = 0; i < 4; i++) { v[i] = xr[threadIdx.x + 256 * i]; s += v[i]; }
    red[threadIdx.x] = s;
    __syncthreads();
    for (int o = 128; o > 0; o >>= 1) {
        if (threadIdx.x < o) red[threadIdx.x] += red[threadIdx.x + o];
        __syncthreads();
    }
    float mu = red[0] * (1.f / C);
    __syncthreads();
    float s2 = 0.f;
#pragma unroll
    for (int i = 0; i < 4; i++) { float d = v[i] - mu; s2 += d * d; }
    red[threadIdx.x] = s2;
    __syncthreads();
    for (int o = 128; o > 0; o >>= 1) {
        if (threadIdx.x < o) red[threadIdx.x] += red[threadIdx.x + o];
        __syncthreads();
    }
    float rstd = rsqrtf(red[0] * (1.f / C) + 1e-5f);
#pragma unroll
    for (int i = 0; i < 4; i++) {
        int c = threadIdx.x + 256 * i;
        float o = (v[i] - mu) * rstd * w[c] + b[c];
        __half h = __float2half(o);
        size_t off = (size_t)row * C + c;
        out_hi[off] = h;
        out_lo[off] = __float2half(o - __half2float(h));
    }
}

// ---------------------------------------------------------------------------
// Split-fp16 tensor-core GEMM via mma.sync — 2 terms: Ah*B + Al*B.
//   A: fp16 hi/lo [M,K]; B: single fp16 [K,N] (weights).
//   512 threads / 16 warps; CTA 128x128; BK=64 (4 ks sub-steps per barrier);
//   warp 4(m)x4(n) of 32x32.  4-stage cp.async pipe (54,272 B/stage).
//   Cross-barrier SWP: next chunk's ks0 fragments preloaded pre-barrier.
// MODE 0 plain | 3 res+acc | 4 res+gate*acc
// MODE 5 fused r/k/v   | MODE 6 fused gate(N=C)/kf(N=F)
// ---------------------------------------------------------------------------
constexpr int BK = 64;
constexpr int SSTRA = 72;                     // A row pad: 64 fp16 -> 144B
constexpr int SSTRB = 136;                    // B row pad (272B)
constexpr int TA = 128 * SSTRA * 2;           // 18432 B
constexpr int TB = BK * SSTRB * 2;            // 17408 B
constexpr int OFF_AH = 0;
constexpr int OFF_AL = TA;
constexpr int OFF_B  = 2 * TA;
constexpr int STAGEB = 2 * TA + TB;           // 54272 B
constexpr int NSTAGE = 4;
constexpr int GEMM_SMEM = NSTAGE * STAGEB;    // 217088 B
constexpr int GTHREADS = 512;

__device__ __forceinline__ uint32_t smem_u32(const void* p) {
    uint32_t a;
    asm("{ .reg .u64 t; cvta.to.shared.u64 t, %1; cvt.u32.u64 %0, t; }"
        : "=r"(a) : "l"(p));
    return a;
}

__device__ __forceinline__ void ldsm_x4(uint32_t addr, uint32_t& r0, uint32_t& r1,
                                        uint32_t& r2, uint32_t& r3) {
    asm volatile("ldmatrix.sync.aligned.m8n8.x4.shared.b16 {%0,%1,%2,%3}, [%4];"
                 : "=r"(r0), "=r"(r1), "=r"(r2), "=r"(r3) : "r"(addr));
}

__device__ __forceinline__ void ldsm_x4_t(uint32_t addr, uint32_t& r0, uint32_t& r1,
                                          uint32_t& r2, uint32_t& r3) {
    asm volatile("ldmatrix.sync.aligned.m8n8.x4.trans.shared.b16 {%0,%1,%2,%3}, [%4];"
                 : "=r"(r0), "=r"(r1), "=r"(r2), "=r"(r3) : "r"(addr));
}

__device__ __forceinline__ void mma_f16(float* d, const uint32_t* a,
                                        uint32_t b0, uint32_t b1) {
    asm volatile(
        "mma.sync.aligned.m16n8k16.row.col.f32.f16.f16.f32 "
        "{%0,%1,%2,%3}, {%4,%5,%6,%7}, {%8,%9}, {%0,%1,%2,%3};"
        : "+f"(d[0]), "+f"(d[1]), "+f"(d[2]), "+f"(d[3])
        : "r"(a[0]), "r"(a[1]), "r"(a[2]), "r"(a[3]), "r"(b0), "r"(b1));
}

__device__ __forceinline__ void cp16(uint32_t sp, const void* gp) {
    asm volatile("cp.async.cg.shared.global [%0], [%1], 16;" :: "r"(sp), "l"(gp));
}

// A tile: 128 rows x 64 k (128B/row). 128 threads: 1 row, 8 cp16 each.
__device__ __forceinline__ void issue_A(uint32_t dst, const __half* __restrict__ g,
                                        int brow, int K, int k0, int t128) {
    int r = t128;
    const __half* gp = g + (size_t)(brow + r) * K + k0;
    uint32_t sp = dst + r * (SSTRA * 2);
#pragma unroll
    for (int cc = 0; cc < 8; cc++)
        cp16(sp + cc * 16, gp + cc * 8);
}

// B tile: 64 k-rows x 128 n (256B/row = 16 chunks). 256 threads: 4 chunks each.
__device__ __forceinline__ void issue_B(uint32_t dst, const __half* __restrict__ g,
                                        int bcol, int Nb, int k0, int q256) {
    int r = q256 >> 2;               // 0..63
    int c0 = (q256 & 3) * 4;         // 0,4,8,12
    const __half* gp = g + (size_t)(k0 + r) * Nb + bcol + c0 * 8;
    uint32_t sp = dst + r * (SSTRB * 2) + c0 * 16;
#pragma unroll
    for (int cc = 0; cc < 4; cc++)
        cp16(sp + cc * 16, gp + cc * 8);
}

template <int MODE>
__global__ __launch_bounds__(GTHREADS, 1) void gemm_mma(
    const __half* __restrict__ Ah, const __half* __restrict__ Al,
    const __half* __restrict__ Bw, const __half* __restrict__ Bw2,
    float* __restrict__ out0,
    __half* __restrict__ outH, __half* __restrict__ outL,
    const float* __restrict__ res, const float* __restrict__ gate,
    int N, int K) {
    extern __shared__ __align__(128) char sm[];
    uint32_t smem = smem_u32(sm);
    int tid = threadIdx.x;
    int wid = tid >> 5;
    int lane = tid & 31;
    int brow = blockIdx.x * 128;

    // ---- mode-dependent B selection / output routing ----
    int bcol, Nb, Nout, epi;
    const __half* BS;
    float* outp = out0;
    if (MODE == 5) {
        int sel = blockIdx.y >> 3;
        bcol = (blockIdx.y & 7) * 128;
        BS = Bw + (size_t)sel * 4 * MB1;
        Nb = N; Nout = N;
        epi = (sel == 0) ? 1 : 0;
        outp = (sel == 0) ? out0 : (sel == 1 ? const_cast<float*>(res)
                                             : const_cast<float*>(gate));
    } else if (MODE == 6) {
        if (blockIdx.y < 8) {
            bcol = blockIdx.y * 128;
            BS = Bw;
            Nb = C; Nout = C;
            epi = 1;
        } else {
            bcol = (blockIdx.y - 8) * 128;
            BS = Bw2;
            Nb = N; Nout = N;          // N = F
            epi = 2;
        }
    } else {
        bcol = blockIdx.y * 128;
        BS = Bw;
        Nb = N; Nout = N;
        epi = MODE;
    }

    int warp_m = wid & 3;          // 0..3 (32 rows each)
    int warp_n = wid >> 2;         // 0..3 (32 cols each)
    int t128 = tid & 127;
    int q256 = tid - 256;

    float acc[2][4][4];
#pragma unroll
    for (int i = 0; i < 2; i++)
#pragma unroll
        for (int j = 0; j < 4; j++)
#pragma unroll
            for (int q = 0; q < 4; q++) acc[i][j][q] = 0.f;

    int nch = K >> 6;              // BK = 64

    // prologue: stages 0..NSTAGE-2 (3 commits)
#pragma unroll
    for (int s = 0; s < NSTAGE - 1; s++) {
        uint32_t sb = smem + s * STAGEB;
        if (tid < 128)       issue_A(sb + OFF_AH, Ah, brow, K, s * BK, t128);
        else if (tid < 256)  issue_A(sb + OFF_AL, Al, brow, K, s * BK, t128);
        else                 issue_B(sb + OFF_B,  BS, bcol, Nb, s * BK, q256);
        asm volatile("cp.async.commit_group;");
    }

    int a_r = (lane & 15);
    int a_k = ((lane >> 4) << 3);
    int b_kr = (lane & 15);
    int b_nf = ((lane >> 4) << 3);

    uint32_t aoffw = (uint32_t)(warp_m * 32 + a_r) * (SSTRA * 2) + a_k * 2;
    uint32_t boffw = (uint32_t)b_kr * (SSTRB * 2) + (warp_n * 32 + b_nf) * 2;
    constexpr uint32_t DAM = 16 * (SSTRA * 2);   // A: +16 m-rows
    constexpr uint32_t DBN = 16 * 2;             // B: +16 n-cols
    constexpr uint32_t DAK = 32;                 // A: +16 k elems (per ks)
    constexpr uint32_t DBK = 16 * (SSTRB * 2);   // B: +16 k-rows (per ks)

    // drain stage 0; publish; preload chunk-0 ks0 fragments
    asm volatile("cp.async.wait_group 2;");
    __syncthreads();

    uint32_t ahc[2][4], bhc[4][2];   // persistent ks0 fragments (current chunk)
    {
        uint32_t aA0 = smem + OFF_AH + aoffw;
        uint32_t bB0 = smem + OFF_B + boffw;
        ldsm_x4(aA0,       ahc[0][0], ahc[0][1], ahc[0][2], ahc[0][3]);
        ldsm_x4(aA0 + DAM, ahc[1][0], ahc[1][1], ahc[1][2], ahc[1][3]);
        uint32_t r0, r1, r2, r3;
        ldsm_x4_t(bB0,       r0, r1, r2, r3);
        bhc[0][0] = r0; bhc[0][1] = r1; bhc[1][0] = r2; bhc[1][1] = r3;
        ldsm_x4_t(bB0 + DBN, r0, r1, r2, r3);
        bhc[2][0] = r0; bhc[2][1] = r1; bhc[3][0] = r2; bhc[3][1] = r3;
    }

#pragma unroll 1
    for (int c = 0; c < nch; c++) {
        uint32_t sbase = smem + (c % NSTAGE) * STAGEB;
        uint32_t aA0 = sbase + OFF_AH + aoffw;
        uint32_t bB0 = sbase + OFF_B + boffw;

        uint32_t al[2][4], ah1[2][4], bh1[4][2];

        // ---- ks0: hh (preloaded) ----
#pragma unroll
        for (int mi = 0; mi < 2; mi++)
#pragma unroll
            for (int ni = 0; ni < 4; ni++)
                mma_f16(acc[mi][ni], ahc[mi], bhc[ni][0], bhc[ni][1]);

        // ks0: A-lo + lh
        ldsm_x4(aA0 + TA,       al[0][0], al[0][1], al[0][2], al[0][3]);
        ldsm_x4(aA0 + TA + DAM, al[1][0], al[1][1], al[1][2], al[1][3]);
#pragma unroll
        for (int mi = 0; mi < 2; mi++)
#pragma unroll
            for (int ni = 0; ni < 4; ni++)
                mma_f16(acc[mi][ni], al[mi], bhc[ni][0], bhc[ni][1]);

        // ---- global prefetch for stage c+3 (one commit per chunk) ----
        if (c + NSTAGE - 1 < nch) {
            uint32_t sb = smem + ((c + NSTAGE - 1) % NSTAGE) * STAGEB;
            int k0 = (c + NSTAGE - 1) * BK;
            if (tid < 128)       issue_A(sb + OFF_AH, Ah, brow, K, k0, t128);
            else if (tid < 256)  issue_A(sb + OFF_AL, Al, brow, K, k0, t128);
            else                 issue_B(sb + OFF_B,  BS, bcol, Nb, k0, q256);
        }
        asm volatile("cp.async.commit_group;");

        // ---- ks1..ks3 ----
#pragma unroll
        for (int ks = 1; ks < 4; ks++) {
            uint32_t dak = (uint32_t)ks * DAK;
            uint32_t dbk = (uint32_t)ks * DBK;
            // hi fragments
            ldsm_x4(aA0 + dak,       ah1[0][0], ah1[0][1], ah1[0][2], ah1[0][3]);
            ldsm_x4(aA0 + dak + DAM, ah1[1][0], ah1[1][1], ah1[1][2], ah1[1][3]);
            {
                uint32_t r0, r1, r2, r3;
                ldsm_x4_t(bB0 + dbk,       r0, r1, r2, r3);
                bh1[0][0] = r0; bh1[0][1] = r1; bh1[1][0] = r2; bh1[1][1] = r3;
                ldsm_x4_t(bB0 + dbk + DBN, r0, r1, r2, r3);
                bh1[2][0] = r0; bh1[2][1] = r1; bh1[3][0] = r2; bh1[3][1] = r3;
            }
            // hh MMAs
#pragma unroll
            for (int mi = 0; mi < 2; mi++)
#pragma unroll
                for (int ni = 0; ni < 4; ni++)
                    mma_f16(acc[mi][ni], ah1[mi], bh1[ni][0], bh1[ni][1]);
            // A-lo
            ldsm_x4(aA0 + dak + TA,       al[0][0], al[0][1], al[0][2], al[0][3]);
            ldsm_x4(aA0 + dak + TA + DAM, al[1][0], al[1][1], al[1][2], al[1][3]);
            if (ks < 3) {
                // lh MMAs for ks1, ks2
#pragma unroll
                for (int mi = 0; mi < 2; mi++)
#pragma unroll
                    for (int ni = 0; ni < 4; ni++)
                        mma_f16(acc[mi][ni], al[mi], bh1[ni][0], bh1[ni][1]);
            }
        }

        // ---- drain so next stage is readable, preload its ks0 fragments ----
        asm volatile("cp.async.wait_group 2;");
        if (c + 1 < nch) {
            uint32_t sbn = smem + ((c + 1) % NSTAGE) * STAGEB;
            uint32_t aN = sbn + OFF_AH + aoffw;
            uint32_t bN = sbn + OFF_B + boffw;
            ldsm_x4(aN,       ahc[0][0], ahc[0][1], ahc[0][2], ahc[0][3]);
            ldsm_x4(aN + DAM, ahc[1][0], ahc[1][1], ahc[1][2], ahc[1][3]);
            uint32_t r0, r1, r2, r3;
            ldsm_x4_t(bN,       r0, r1, r2, r3);
            bhc[0][0] = r0; bhc[0][1] = r1; bhc[1][0] = r2; bhc[1][1] = r3;
            ldsm_x4_t(bN + DBN, r0, r1, r2, r3);
            bhc[2][0] = r0; bhc[2][1] = r1; bhc[3][0] = r2; bhc[3][1] = r3;
        }

        // barrier BEFORE tail MMAs (ks3 lh)
        __syncthreads();

#pragma unroll
        for (int mi = 0; mi < 2; mi++)
#pragma unroll
            for (int ni = 0; ni < 4; ni++)
                mma_f16(acc[mi][ni], al[mi], bh1[ni][0], bh1[ni][1]);
    }

    // ---- epilogue ----
    int qrow = lane >> 2;
    int qcol = (lane & 3) * 2;
#pragma unroll
    for (int mi = 0; mi < 2; mi++) {
#pragma unroll
        for (int h = 0; h < 2; h++) {
            int row = brow + warp_m * 32 + mi * 16 + qrow + h * 8;
#pragma unroll
            for (int ni = 0; ni < 4; ni++) {
                int col = bcol + warp_n * 32 + ni * 8 + qcol;
                size_t off = (size_t)row * Nout + col;
                float o0 = acc[mi][ni][h * 2];
                float o1 = acc[mi][ni][h * 2 + 1];
                if (MODE == 3) {
                    const float2 rv = *(const float2*)(res + off);
                    o0 += rv.x; o1 += rv.y;
                } else if (MODE == 4) {
                    const float2 rv = *(const float2*)(res + off);
                    const float2 gv = *(const float2*)(gate + off);
                    o0 = rv.x + gv.x * o0;
                    o1 = rv.y + gv.y * o1;
                } else if (epi == 1) {
                    o0 = 1.f / (1.f + expf(-o0));
                    o1 = 1.f / (1.f + expf(-o1));
                }
                if (epi == 2) {
                    o0 = fmaxf(o0, 0.f); o0 *= o0;
                    o1 = fmaxf(o1, 0.f); o1 *= o1;
                    __half h0 = __float2half(o0);
                    __half h1 = __float2half(o1);
                    __half2 hp; hp.x = h0; hp.y = h1;
                    __half2 lp;
                    lp.x = __float2half(o0 - __half2float(h0));
                    lp.y = __float2half(o1 - __half2float(h1));
                    *(__half2*)(outH + off) = hp;
                    *(__half2*)(outL + off) = lp;
                } else {
                    float2 ov = make_float2(o0, o1);
                    *(float2*)(outp + off) = ov;
                }
            }
        }
    }
}

// ---------------------------------------------------------------------------
// Chunk-parallel bidirectional WKV (3 kernels); y output = split fp16.
// ---------------------------------------------------------------------------
__global__ __launch_bounds__(256) void wkv_agg_k(
    const float* __restrict__ k, const float* __restrict__ v,
    const float* __restrict__ w,
    float* __restrict__ aFkv, float* __restrict__ aFk,
    float* __restrict__ aBkv, float* __restrict__ aBk) {
    int gid = blockIdx.x * blockDim.x + threadIdx.x;
    int c = gid & (C - 1);
    int ch = (gid >> 10) & (CH - 1);
    int b = gid >> 14;
    float d = expf(-expf(w[c]));
    size_t base = (size_t)b * T * C + (size_t)ch * CL * C + c;

    float fkv = 0.f, fk = 0.f, bkv = 0.f, bk = 0.f, pw = 1.f;
#pragma unroll 4
    for (int i = 0; i < CL; i++) {
        size_t o = base + (size_t)i * C;
        float ek = expf(k[o]);
        float kv = ek * v[o];
        fkv = fkv * d + kv;
        fk  = fk  * d + ek;
        bkv += kv * pw;
        bk  += ek * pw;
        pw *= d;
    }
    aFkv[gid] = fkv; aFk[gid] = fk;
    aBkv[gid] = bkv; aBk[gid] = bk;
}

__global__ __launch_bounds__(256) void wkv_scan_k(
    const float* __restrict__ w,
    const float* __restrict__ aFkv, const float* __restrict__ aFk,
    const float* __restrict__ aBkv, const float* __restrict__ aBk,
    float* __restrict__ iFkv, float* __restrict__ iFk,
    float* __restrict__ iBkv, float* __restrict__ iBk) {
    int gid = blockIdx.x * blockDim.x + threadIdx.x;
    int c = gid & (C - 1);
    int b = gid >> 10;
    float D = expf(-(float)CL * expf(w[c]));
    int base = b * CH * C + c;

    float skv = 0.f, sk = 0.f;
#pragma unroll
    for (int ch = 0; ch < CH; ch++) {
        int ai = base + ch * C;
        iFkv[ai] = skv; iFk[ai] = sk;
        skv = skv * D + aFkv[ai];
        sk  = sk  * D + aFk[ai];
    }
    skv = 0.f; sk = 0.f;
#pragma unroll
    for (int ch = CH - 1; ch >= 0; ch--) {
        int ai = base + ch * C;
        iBkv[ai] = skv; iBk[ai] = sk;
        skv = skv * D + aBkv[ai];
        sk  = sk  * D + aBk[ai];
    }
}

__global__ __launch_bounds__(256) void wkv_apply_k(
    const float* __restrict__ r, const float* __restrict__ k,
    const float* __restrict__ v, const float* __restrict__ w,
    const float* __restrict__ u,
    const float* __restrict__ iFkv, const float* __restrict__ iFk,
    const float* __restrict__ iBkv, const float* __restrict__ iBk,
    __half* __restrict__ y_hi, __half* __restrict__ y_lo,
    float* __restrict__ sakv, float* __restrict__ sak) {
    int gid = blockIdx.x * blockDim.x + threadIdx.x;
    int c = gid & (C - 1);
    int ch = (gid >> 10) & (CH - 1);
    int b = gid >> 14;
    float d = expf(-expf(w[c]));
    float eu = expf(u[c]);
    size_t base = (size_t)b * T * C + (size_t)ch * CL * C + c;

    float fkv = iFkv[gid], fk = iFk[gid];
#pragma unroll 4
    for (int i = 0; i < CL; i++) {
        size_t o = base + (size_t)i * C;
        float ek = expf(k[o]);
        float kv = ek * v[o];
        sakv[o] = fkv;
        sak[o]  = fk;
        fkv = fkv * d + kv;
        fk  = fk  * d + ek;
    }
    float bkv = iBkv[gid], bk = iBk[gid];
#pragma unroll 4
    for (int i = CL - 1; i >= 0; i--) {
        size_t o = base + (size_t)i * C;
        float vv = v[o];
        float ek = expf(k[o]);
        float kv = ek * vv;
        float num = sakv[o] + bkv + eu * vv;
        float den = sak[o]  + bk  + eu;
        float yv = r[o] * num / (den + 1e-8f);
        __half h = __float2half(yv);
        y_hi[o] = h;
        y_lo[o] = __float2half(yv - __half2float(h));
        bkv = bkv * d + kv;
        bk  = bk  * d + ek;
    }
}

// ---------------------------------------------------------------------------
// Host launch
// ---------------------------------------------------------------------------
extern "C" void kernel_launch(void* const* d_in, const int* in_sizes, int n_in,
                              void* d_out, int out_size) {
    const int*   idx     = (const int*)  d_in[0];
    const float* emb     = (const float*)d_in[1];
    const float* ln1_w   = (const float*)d_in[2];
    const float* ln1_b   = (const float*)d_in[3];
    const float* Wr      = (const float*)d_in[4];
    const float* Wk      = (const float*)d_in[5];
    const float* Wv      = (const float*)d_in[6];
    const float* w_decay = (const float*)d_in[7];
    const float* u_bonus = (const float*)d_in[8];
    const float* Wo      = (const float*)d_in[9];
    const float* ln2_w   = (const float*)d_in[10];
    const float* ln2_b   = (const float*)d_in[11];
    const float* Wfk     = (const float*)d_in[12];
    const float* Wfv     = (const float*)d_in[13];
    const float* Wfr     = (const float*)d_in[14];
    const float* lnout_w = (const float*)d_in[15];
    const float* lnout_b = (const float*)d_in[16];
    const float* head_W  = (const float*)d_in[17];
    float* out = (float*)d_out;

    float *x, *r, *k, *v, *sa, *sb;
    float *aFkv, *aFk, *aBkv, *aBk, *iFkv, *iFk, *iBkv, *iBk;
    __half *wt, *xnh, *xnl, *yh, *yl, *kfh, *kfl;
    cudaGetSymbolAddress((void**)&x,    g_x);
    cudaGetSymbolAddress((void**)&r,    g_r);
    cudaGetSymbolAddress((void**)&k,    g_k);
    cudaGetSymbolAddress((void**)&v,    g_v);
    cudaGetSymbolAddress((void**)&sa,   g_sakv);
    cudaGetSymbolAddress((void**)&sb,   g_sak);
    cudaGetSymbolAddress((void**)&wt,   g_wt);
    cudaGetSymbolAddress((void**)&xnh,  g_xn_hi);
    cudaGetSymbolAddress((void**)&xnl,  g_xn_lo);
    cudaGetSymbolAddress((void**)&yh,   g_y_hi);
    cudaGetSymbolAddress((void**)&yl,   g_y_lo);
    cudaGetSymbolAddress((void**)&kfh,  g_kf_hi);
    cudaGetSymbolAddress((void**)&kfl,  g_kf_lo);
    cudaGetSymbolAddress((void**)&aFkv, g_aggFkv);
    cudaGetSymbolAddress((void**)&aFk,  g_aggFk);
    cudaGetSymbolAddress((void**)&aBkv, g_aggBkv);
    cudaGetSymbolAddress((void**)&aBk,  g_aggBk);
    cudaGetSymbolAddress((void**)&iFkv, g_iniFkv);
    cudaGetSymbolAddress((void**)&iFk,  g_iniFk);
    cudaGetSymbolAddress((void**)&iBkv, g_iniBkv);
    cudaGetSymbolAddress((void**)&iBk,  g_iniBk);

    cudaFuncSetAttribute(gemm_mma<0>, cudaFuncAttributeMaxDynamicSharedMemorySize, GEMM_SMEM);
    cudaFuncSetAttribute(gemm_mma<3>, cudaFuncAttributeMaxDynamicSharedMemorySize, GEMM_SMEM);
    cudaFuncSetAttribute(gemm_mma<4>, cudaFuncAttributeMaxDynamicSharedMemorySize, GEMM_SMEM);
    cudaFuncSetAttribute(gemm_mma<5>, cudaFuncAttributeMaxDynamicSharedMemorySize, GEMM_SMEM);
    cudaFuncSetAttribute(gemm_mma<6>, cudaFuncAttributeMaxDynamicSharedMemorySize, GEMM_SMEM);

    convert_all_k<<<4096, 256>>>((const float4*)Wr, (const float4*)Wk,
                                 (const float4*)Wv, (const float4*)Wo,
                                 (const float4*)Wfr, (const float4*)Wfk,
                                 (const float4*)Wfv, (const float4*)head_W,
                                 (uint4*)wt);

    embed_k<<<M, 256>>>(idx, emb, x);

    dim3 gRKV(M / 128, 24);        // fused r/k/v     (384 CTAs)
    dim3 gCM (M / 128, 40);        // fused gate/kf   (640 CTAs)
    dim3 gCCg(M / 128, C / 128);   // 16 x 8
    dim3 gCVg(M / 128, V / 128);   // 16 x 393

    for (int l = 0; l < L; l++) {
        size_t wcc = (size_t)l * C * C;
        size_t wcf = (size_t)l * C * F;
        const float* l1w = ln1_w + (size_t)l * C;
        const float* l1b = ln1_b + (size_t)l * C;
        const float* wd  = w_decay + (size_t)l * C;
        const float* ub  = u_bonus + (size_t)l * C;
        const float* l2w = ln2_w + (size_t)l * C;
        const float* l2b = ln2_b + (size_t)l * C;

        // time-mix
        layernorm_k<<<M, 256>>>(x, l1w, l1b, xnh, xnl);
        gemm_mma<5><<<gRKV, GTHREADS, GEMM_SMEM>>>(
            xnh, xnl, wt + O_WR + wcc, nullptr,
            r, nullptr, nullptr, k, v, C, C);
        wkv_agg_k<<<(B * CH * C) / 256, 256>>>(k, v, wd, aFkv, aFk, aBkv, aBk);
        wkv_scan_k<<<(B * C) / 256, 256>>>(wd, aFkv, aFk, aBkv, aBk,
                                           iFkv, iFk, iBkv, iBk);
        wkv_apply_k<<<(B * CH * C) / 256, 256>>>(r, k, v, wd, ub,
                                                 iFkv, iFk, iBkv, iBk,
                                                 yh, yl, sa, sb);
        gemm_mma<3><<<gCCg, GTHREADS, GEMM_SMEM>>>(
            yh, yl, wt + O_WO + wcc, nullptr,
            x, nullptr, nullptr, x, nullptr, C, C);

        // channel-mix
        layernorm_k<<<M, 256>>>(x, l2w, l2b, xnh, xnl);
        gemm_mma<6><<<gCM, GTHREADS, GEMM_SMEM>>>(
            xnh, xnl, wt + O_WFR + wcc, wt + O_WFK + wcf,
            r, kfh, kfl, nullptr, nullptr, F, C);
        gemm_mma<4><<<gCCg, GTHREADS, GEMM_SMEM>>>(
            kfh, kfl, wt + O_WFV + wcf, nullptr,
            x, nullptr, nullptr, x, r, C, F);
    }

    layernorm_k<<<M, 256>>>(x, lnout_w, lnout_b, xnh, xnl);
    gemm_mma<0><<<gCVg, GTHREADS, GEMM_SMEM>>>(
        xnh, xnl, wt + O_HEAD, nullptr,
        out, nullptr, nullptr, nullptr, nullptr, V, C);
}

// round 15
// speedup vs baseline: 1.1450x; 1.1450x over previous
#include <cuda_runtime.h>
#include <cuda_bf16.h>
#include <cuda_fp16.h>
#include <cstdint>
#include <math.h>

// ---------------------------------------------------------------------------
// Problem constants
// ---------------------------------------------------------------------------
constexpr int L = 4;
constexpr int C = 1024;
constexpr int F = 4096;
constexpr int V = 50304;
constexpr int B = 2;
constexpr int T = 1024;
constexpr int M = B * T;            // 2048 rows
constexpr int CH = 16;              // wkv chunks
constexpr int CL = 64;              // wkv chunk length

// ---------------------------------------------------------------------------
// Converted-weight layout: single fp16, SAME [K,N] layout as inputs.
// ---------------------------------------------------------------------------
constexpr size_t MB1 = size_t(C) * C;         // 1,048,576
constexpr size_t O_WR   = 0;                  // [L][C][C]  (Wk = +4MB1, Wv = +8MB1)
constexpr size_t O_WK   = 4 * MB1;
constexpr size_t O_WV   = 8 * MB1;
constexpr size_t O_WO   = 12 * MB1;
constexpr size_t O_WFR  = 16 * MB1;
constexpr size_t O_WFK  = 20 * MB1;           // [L][C][F]
constexpr size_t O_WFV  = 36 * MB1;           // [L][F][C]
constexpr size_t O_HEAD = 52 * MB1;           // [C][V]
constexpr size_t WTOTAL = O_HEAD + size_t(V) * C;

__device__ alignas(16) __half g_wt[WTOTAL];

__device__ alignas(16) float g_x   [size_t(M) * C];
__device__ alignas(16) float g_r   [size_t(M) * C];
__device__ alignas(16) float g_k   [size_t(M) * C];
__device__ alignas(16) float g_v   [size_t(M) * C];
__device__ alignas(16) float g_sakv[size_t(M) * C];
__device__ alignas(16) float g_sak [size_t(M) * C];
__device__ alignas(16) __half g_xn_hi[size_t(M) * C];
__device__ alignas(16) __half g_xn_lo[size_t(M) * C];
__device__ alignas(16) __half g_y_hi [size_t(M) * C];
__device__ alignas(16) __half g_y_lo [size_t(M) * C];
__device__ alignas(16) __half g_kf_hi[size_t(M) * F];
__device__ alignas(16) __half g_kf_lo[size_t(M) * F];

// wkv chunk-scan scratch: [B][CH][C]
constexpr int AGG = B * CH * C;    // 32768
__device__ alignas(16) float g_aggFkv[AGG];
__device__ alignas(16) float g_aggFk [AGG];
__device__ alignas(16) float g_aggBkv[AGG];
__device__ alignas(16) float g_aggBk [AGG];
__device__ alignas(16) float g_iniFkv[AGG];
__device__ alignas(16) float g_iniFk [AGG];
__device__ alignas(16) float g_iniBkv[AGG];
__device__ alignas(16) float g_iniBk [AGG];

// ---------------------------------------------------------------------------
// Merged streaming conversion: fp32 -> single fp16, 16B stores.
// ---------------------------------------------------------------------------
constexpr size_t N4_CC = size_t(L) * C * C / 4;
constexpr size_t N4_CF = size_t(L) * C * F / 4;
constexpr size_t N4_HD = size_t(V) * C / 4;
constexpr size_t CV_B0 = N4_CC;
constexpr size_t CV_B1 = CV_B0 + N4_CC;
constexpr size_t CV_B2 = CV_B1 + N4_CC;
constexpr size_t CV_B3 = CV_B2 + N4_CC;
constexpr size_t CV_B4 = CV_B3 + N4_CC;
constexpr size_t CV_B5 = CV_B4 + N4_CF;
constexpr size_t CV_B6 = CV_B5 + N4_CF;
constexpr size_t CV_TOT = CV_B6 + N4_HD;
constexpr size_t CV_G = CV_TOT / 2;           // groups of 2 float4 (8 floats)

__device__ __forceinline__ uint32_t pack_h2(float a, float b) {
    __half2 h;
    h.x = __float2half(a);
    h.y = __float2half(b);
    return *(uint32_t*)&h;
}

__global__ __launch_bounds__(256) void convert_all_k(
    const float4* __restrict__ wr, const float4* __restrict__ wk,
    const float4* __restrict__ wv, const float4* __restrict__ wo,
    const float4* __restrict__ wfr, const float4* __restrict__ wfk,
    const float4* __restrict__ wfv, const float4* __restrict__ hd,
    uint4* __restrict__ oh) {
    size_t stride = (size_t)gridDim.x * blockDim.x;
    for (size_t g = (size_t)blockIdx.x * blockDim.x + threadIdx.x; g < CV_G;
         g += stride) {
        size_t i = 2 * g;
        const float4* src;
        size_t dstg;   // uint4 index (8 halves)
        if (i < CV_B0)      { src = wr  + i;            dstg = O_WR  / 8 + g; }
        else if (i < CV_B1) { src = wk  + (i - CV_B0);  dstg = O_WK  / 8 + (g - CV_B0 / 2); }
        else if (i < CV_B2) { src = wv  + (i - CV_B1);  dstg = O_WV  / 8 + (g - CV_B1 / 2); }
        else if (i < CV_B3) { src = wo  + (i - CV_B2);  dstg = O_WO  / 8 + (g - CV_B2 / 2); }
        else if (i < CV_B4) { src = wfr + (i - CV_B3);  dstg = O_WFR / 8 + (g - CV_B3 / 2); }
        else if (i < CV_B5) { src = wfk + (i - CV_B4);  dstg = O_WFK / 8 + (g - CV_B4 / 2); }
        else if (i < CV_B6) { src = wfv + (i - CV_B5);  dstg = O_WFV / 8 + (g - CV_B5 / 2); }
        else                { src = hd  + (i - CV_B6);  dstg = O_HEAD/ 8 + (g - CV_B6 / 2); }
        float4 w0 = src[0];
        float4 w1 = src[1];
        uint4 H;
        H.x = pack_h2(w0.x, w0.y);
        H.y = pack_h2(w0.z, w0.w);
        H.z = pack_h2(w1.x, w1.y);
        H.w = pack_h2(w1.z, w1.w);
        oh[dstg] = H;
    }
}

// ---------------------------------------------------------------------------
// Embedding gather
// ---------------------------------------------------------------------------
__global__ void embed_k(const int* __restrict__ idx,
                        const float* __restrict__ emb,
                        float* __restrict__ x) {
    int row = blockIdx.x;
    int id = idx[row];
    const float4* src = (const float4*)(emb + (size_t)id * C);
    float4* dst = (float4*)(x + (size_t)row * C);
    for (int i = threadIdx.x; i < C / 4; i += blockDim.x) dst[i] = src[i];
}

// ---------------------------------------------------------------------------
// LayerNorm -> split fp16 output (hi + residual lo)
// ---------------------------------------------------------------------------
__global__ __launch_bounds__(256) void layernorm_k(const float* __restrict__ x,
                                                   const float* __restrict__ w,
                                                   const float* __restrict__ b,
                                                   __half* __restrict__ out_hi,
                                                   __half* __restrict__ out_lo) {
    __shared__ float red[256];
    int row = blockIdx.x;
    const float* xr = x + (size_t)row * C;
    float v[4];
    float s = 0.f;
#pragma unroll
    for (int i = 0; i < 4; i++) { v[i] = xr[threadIdx.x + 256 * i]; s += v[i]; }
    red[threadIdx.x] = s;
    __syncthreads();
    for (int o = 128; o > 0; o >>= 1) {
        if (threadIdx.x < o) red[threadIdx.x] += red[threadIdx.x + o];
        __syncthreads();
    }
    float mu = red[0] * (1.f / C);
    __syncthreads();
    float s2 = 0.f;
#pragma unroll
    for (int i = 0; i < 4; i++) { float d = v[i] - mu; s2 += d * d; }
    red[threadIdx.x] = s2;
    __syncthreads();
    for (int o = 128; o > 0; o >>= 1) {
        if (threadIdx.x < o) red[threadIdx.x] += red[threadIdx.x + o];
        __syncthreads();
    }
    float rstd = rsqrtf(red[0] * (1.f / C) + 1e-5f);
#pragma unroll
    for (int i = 0; i < 4; i++) {
        int c = threadIdx.x + 256 * i;
        float o = (v[i] - mu) * rstd * w[c] + b[c];
        __half h = __float2half(o);
        size_t off = (size_t)row * C + c;
        out_hi[off] = h;
        out_lo[off] = __float2half(o - __half2float(h));
    }
}

// ---------------------------------------------------------------------------
// Split-fp16 tensor-core GEMM via mma.sync — 2 MMA terms: Ah*B + Al*B.
//   A: fp16 hi/lo [M,K]; B: single fp16 [K,N] (weights).
//   512 threads / 16 warps; CTA 128x128; BK=32; warp 4(m)x4(n) of 32x32.
//   6-stage cp.async pipe; next chunk's ks0 fragments preloaded across barrier.
//   wait_group 4 keeps 4 groups in flight (drain only what the preload needs).
// MODE 0 plain | 3 res+acc | 4 res+gate*acc
// MODE 5 fused r/k/v   | MODE 6 fused gate(N=C)/kf(N=F)
// ---------------------------------------------------------------------------
constexpr int BK = 32;
constexpr int SSTRA = 40;                     // A row pad (80B)
constexpr int SSTRB = 136;                    // B row pad (272B)
constexpr int TA = 128 * SSTRA * 2;           // 10240 B
constexpr int TB = BK * SSTRB * 2;            // 8704 B
constexpr int OFF_AH = 0;
constexpr int OFF_AL = TA;
constexpr int OFF_B  = 2 * TA;
constexpr int STAGEB = 2 * TA + TB;           // 29184 B
constexpr int NSTAGE = 6;
constexpr int GEMM_SMEM = NSTAGE * STAGEB;    // 175104 B
constexpr int GTHREADS = 512;

__device__ __forceinline__ uint32_t smem_u32(const void* p) {
    uint32_t a;
    asm("{ .reg .u64 t; cvta.to.shared.u64 t, %1; cvt.u32.u64 %0, t; }"
        : "=r"(a) : "l"(p));
    return a;
}

__device__ __forceinline__ void ldsm_x4(uint32_t addr, uint32_t& r0, uint32_t& r1,
                                        uint32_t& r2, uint32_t& r3) {
    asm volatile("ldmatrix.sync.aligned.m8n8.x4.shared.b16 {%0,%1,%2,%3}, [%4];"
                 : "=r"(r0), "=r"(r1), "=r"(r2), "=r"(r3) : "r"(addr));
}

__device__ __forceinline__ void ldsm_x4_t(uint32_t addr, uint32_t& r0, uint32_t& r1,
                                          uint32_t& r2, uint32_t& r3) {
    asm volatile("ldmatrix.sync.aligned.m8n8.x4.trans.shared.b16 {%0,%1,%2,%3}, [%4];"
                 : "=r"(r0), "=r"(r1), "=r"(r2), "=r"(r3) : "r"(addr));
}

__device__ __forceinline__ void mma_f16(float* d, const uint32_t* a,
                                        uint32_t b0, uint32_t b1) {
    asm volatile(
        "mma.sync.aligned.m16n8k16.row.col.f32.f16.f16.f32 "
        "{%0,%1,%2,%3}, {%4,%5,%6,%7}, {%8,%9}, {%0,%1,%2,%3};"
        : "+f"(d[0]), "+f"(d[1]), "+f"(d[2]), "+f"(d[3])
        : "r"(a[0]), "r"(a[1]), "r"(a[2]), "r"(a[3]), "r"(b0), "r"(b1));
}

__device__ __forceinline__ void cp16(uint32_t sp, const void* gp) {
    asm volatile("cp.async.cg.shared.global [%0], [%1], 16;" :: "r"(sp), "l"(gp));
}

// A tile: 128 rows x 32 k (64B/row). 128 threads: 1 row, 4 cp16 each.
__device__ __forceinline__ void issue_A(uint32_t dst, const __half* __restrict__ g,
                                        int brow, int K, int k0, int t128) {
    int r = t128;
    const __half* gp = g + (size_t)(brow + r) * K + k0;
    uint32_t sp = dst + r * (SSTRA * 2);
#pragma unroll
    for (int cc = 0; cc < 4; cc++)
        cp16(sp + cc * 16, gp + cc * 8);
}

// B tile: 32 k-rows x 128 n (256B/row = 16 chunks). 256 threads: 2 chunks each.
__device__ __forceinline__ void issue_B(uint32_t dst, const __half* __restrict__ g,
                                        int bcol, int Nb, int k0, int q256) {
    int r = q256 >> 3;               // 0..31
    int c0 = (q256 & 7) * 2;         // chunk index 0..14 step 2
    const __half* gp = g + (size_t)(k0 + r) * Nb + bcol + c0 * 8;
    uint32_t sp = dst + r * (SSTRB * 2) + c0 * 16;
#pragma unroll
    for (int cc = 0; cc < 2; cc++)
        cp16(sp + cc * 16, gp + cc * 8);
}

template <int MODE>
__global__ __launch_bounds__(GTHREADS, 1) void gemm_mma(
    const __half* __restrict__ Ah, const __half* __restrict__ Al,
    const __half* __restrict__ Bw, const __half* __restrict__ Bw2,
    float* __restrict__ out0,
    __half* __restrict__ outH, __half* __restrict__ outL,
    const float* __restrict__ res, const float* __restrict__ gate,
    int N, int K) {
    extern __shared__ __align__(128) char sm[];
    uint32_t smem = smem_u32(sm);
    int tid = threadIdx.x;
    int wid = tid >> 5;
    int lane = tid & 31;
    int brow = blockIdx.x * 128;

    // ---- mode-dependent B selection / output routing ----
    int bcol, Nb, Nout, epi;
    const __half* BS;
    float* outp = out0;
    if (MODE == 5) {
        int sel = blockIdx.y >> 3;
        bcol = (blockIdx.y & 7) * 128;
        BS = Bw + (size_t)sel * 4 * MB1;
        Nb = N; Nout = N;
        epi = (sel == 0) ? 1 : 0;
        outp = (sel == 0) ? out0 : (sel == 1 ? const_cast<float*>(res)
                                             : const_cast<float*>(gate));
    } else if (MODE == 6) {
        if (blockIdx.y < 8) {
            bcol = blockIdx.y * 128;
            BS = Bw;
            Nb = C; Nout = C;
            epi = 1;
        } else {
            bcol = (blockIdx.y - 8) * 128;
            BS = Bw2;
            Nb = N; Nout = N;          // N = F
            epi = 2;
        }
    } else {
        bcol = blockIdx.y * 128;
        BS = Bw;
        Nb = N; Nout = N;
        epi = MODE;
    }

    int warp_m = wid & 3;          // 0..3 (32 rows each)
    int warp_n = wid >> 2;         // 0..3 (32 cols each)
    // loader roles: tid<128 -> Ah, <256 -> Al, else B (q = tid-256)
    int t128 = tid & 127;
    int q256 = tid - 256;

    float acc[2][4][4];
#pragma unroll
    for (int i = 0; i < 2; i++)
#pragma unroll
        for (int j = 0; j < 4; j++)
#pragma unroll
            for (int q = 0; q < 4; q++) acc[i][j][q] = 0.f;

    int nch = K >> 5;              // BK = 32

    // prologue: stages 0..NSTAGE-2 (5 commits)
#pragma unroll
    for (int s = 0; s < NSTAGE - 1; s++) {
        uint32_t sb = smem + s * STAGEB;
        if (tid < 128)       issue_A(sb + OFF_AH, Ah, brow, K, s * BK, t128);
        else if (tid < 256)  issue_A(sb + OFF_AL, Al, brow, K, s * BK, t128);
        else                 issue_B(sb + OFF_B,  BS, bcol, Nb, s * BK, q256);
        asm volatile("cp.async.commit_group;");
    }

    int a_r = (lane & 15);
    int a_k = ((lane >> 4) << 3);
    int b_kr = (lane & 15);
    int b_nf = ((lane >> 4) << 3);

    uint32_t aoffw = (uint32_t)(warp_m * 32 + a_r) * (SSTRA * 2) + a_k * 2;
    uint32_t boffw = (uint32_t)b_kr * (SSTRB * 2) + (warp_n * 32 + b_nf) * 2;
    constexpr uint32_t DAM = 16 * (SSTRA * 2);   // A: +16 m-rows
    constexpr uint32_t DBN = 16 * 2;             // B: +16 n-cols
    constexpr uint32_t DAK = 32;                 // A: ks1 (+16 k elems)
    constexpr uint32_t DBK = 16 * (SSTRB * 2);   // B: ks1 (+16 k-rows)

    // drain only stage 0; publish; preload chunk-0 ks0 fragments
    asm volatile("cp.async.wait_group 4;");
    __syncthreads();

    uint32_t ahc[2][4], bhc[4][2];   // persistent ks0 fragments (current chunk)
    {
        uint32_t aA0 = smem + OFF_AH + aoffw;
        uint32_t bB0 = smem + OFF_B + boffw;
        ldsm_x4(aA0,       ahc[0][0], ahc[0][1], ahc[0][2], ahc[0][3]);
        ldsm_x4(aA0 + DAM, ahc[1][0], ahc[1][1], ahc[1][2], ahc[1][3]);
        uint32_t r0, r1, r2, r3;
        ldsm_x4_t(bB0,       r0, r1, r2, r3);
        bhc[0][0] = r0; bhc[0][1] = r1; bhc[1][0] = r2; bhc[1][1] = r3;
        ldsm_x4_t(bB0 + DBN, r0, r1, r2, r3);
        bhc[2][0] = r0; bhc[2][1] = r1; bhc[3][0] = r2; bhc[3][1] = r3;
    }

#pragma unroll 1
    for (int c = 0; c < nch; c++) {
        uint32_t sbase = smem + (c % NSTAGE) * STAGEB;
        uint32_t aA0 = sbase + OFF_AH + aoffw;
        uint32_t bB0 = sbase + OFF_B + boffw;

        uint32_t al[2][4], ah1[2][4], bh1[4][2];

        // 1) hh0 MMAs — fragments already in registers
#pragma unroll
        for (int mi = 0; mi < 2; mi++)
#pragma unroll
            for (int ni = 0; ni < 4; ni++)
                mma_f16(acc[mi][ni], ahc[mi], bhc[ni][0], bhc[ni][1]);

        // 2) LDSM ks0 A-lo
        ldsm_x4(aA0 + TA,       al[0][0], al[0][1], al[0][2], al[0][3]);
        ldsm_x4(aA0 + TA + DAM, al[1][0], al[1][1], al[1][2], al[1][3]);

        // 3) lh0 MMAs
#pragma unroll
        for (int mi = 0; mi < 2; mi++)
#pragma unroll
            for (int ni = 0; ni < 4; ni++)
                mma_f16(acc[mi][ni], al[mi], bhc[ni][0], bhc[ni][1]);

        // 4) LDSM ks1 A-hi and B
        ldsm_x4(aA0 + DAK,       ah1[0][0], ah1[0][1], ah1[0][2], ah1[0][3]);
        ldsm_x4(aA0 + DAK + DAM, ah1[1][0], ah1[1][1], ah1[1][2], ah1[1][3]);
        {
            uint32_t r0, r1, r2, r3;
            ldsm_x4_t(bB0 + DBK,       r0, r1, r2, r3);
            bh1[0][0] = r0; bh1[0][1] = r1; bh1[1][0] = r2; bh1[1][1] = r3;
            ldsm_x4_t(bB0 + DBK + DBN, r0, r1, r2, r3);
            bh1[2][0] = r0; bh1[2][1] = r1; bh1[3][0] = r2; bh1[3][1] = r3;
        }

        // 5) global prefetch for stage c+5 (one commit per chunk)
        if (c + NSTAGE - 1 < nch) {
            uint32_t sb = smem + ((c + NSTAGE - 1) % NSTAGE) * STAGEB;
            int k0 = (c + NSTAGE - 1) * BK;
            if (tid < 128)       issue_A(sb + OFF_AH, Ah, brow, K, k0, t128);
            else if (tid < 256)  issue_A(sb + OFF_AL, Al, brow, K, k0, t128);
            else                 issue_B(sb + OFF_B,  BS, bcol, Nb, k0, q256);
        }
        asm volatile("cp.async.commit_group;");

        // 6) hh1 MMAs
#pragma unroll
        for (int mi = 0; mi < 2; mi++)
#pragma unroll
            for (int ni = 0; ni < 4; ni++)
                mma_f16(acc[mi][ni], ah1[mi], bh1[ni][0], bh1[ni][1]);

        // 7) LDSM ks1 A-lo (reuse al)
        ldsm_x4(aA0 + DAK + TA,       al[0][0], al[0][1], al[0][2], al[0][3]);
        ldsm_x4(aA0 + DAK + TA + DAM, al[1][0], al[1][1], al[1][2], al[1][3]);

        // 8) drain only down to the preload target (keep 4 groups in flight)
        asm volatile("cp.async.wait_group 4;");
        if (c + 1 < nch) {
            uint32_t sbn = smem + ((c + 1) % NSTAGE) * STAGEB;
            uint32_t aN = sbn + OFF_AH + aoffw;
            uint32_t bN = sbn + OFF_B + boffw;
            ldsm_x4(aN,       ahc[0][0], ahc[0][1], ahc[0][2], ahc[0][3]);
            ldsm_x4(aN + DAM, ahc[1][0], ahc[1][1], ahc[1][2], ahc[1][3]);
            uint32_t r0, r1, r2, r3;
            ldsm_x4_t(bN,       r0, r1, r2, r3);
            bhc[0][0] = r0; bhc[0][1] = r1; bhc[1][0] = r2; bhc[1][1] = r3;
            ldsm_x4_t(bN + DBN, r0, r1, r2, r3);
            bhc[2][0] = r0; bhc[2][1] = r1; bhc[3][0] = r2; bhc[3][1] = r3;
        }

        // 9) barrier BEFORE tail MMAs
        __syncthreads();

        // 10) lh1 MMAs
#pragma unroll
        for (int mi = 0; mi < 2; mi++)
#pragma unroll
            for (int ni = 0; ni < 4; ni++)
                mma_f16(acc[mi][ni], al[mi], bh1[ni][0], bh1[ni][1]);
    }

    // ---- epilogue ----
    int qrow = lane >> 2;
    int qcol = (lane & 3) * 2;
#pragma unroll
    for (int mi = 0; mi < 2; mi++) {
#pragma unroll
        for (int h = 0; h < 2; h++) {
            int row = brow + warp_m * 32 + mi * 16 + qrow + h * 8;
#pragma unroll
            for (int ni = 0; ni < 4; ni++) {
                int col = bcol + warp_n * 32 + ni * 8 + qcol;
                size_t off = (size_t)row * Nout + col;
                float o0 = acc[mi][ni][h * 2];
                float o1 = acc[mi][ni][h * 2 + 1];
                if (MODE == 3) {
                    const float2 rv = *(const float2*)(res + off);
                    o0 += rv.x; o1 += rv.y;
                } else if (MODE == 4) {
                    const float2 rv = *(const float2*)(res + off);
                    const float2 gv = *(const float2*)(gate + off);
                    o0 = rv.x + gv.x * o0;
                    o1 = rv.y + gv.y * o1;
                } else if (epi == 1) {
                    o0 = 1.f / (1.f + expf(-o0));
                    o1 = 1.f / (1.f + expf(-o1));
                }
                if (epi == 2) {
                    o0 = fmaxf(o0, 0.f); o0 *= o0;
                    o1 = fmaxf(o1, 0.f); o1 *= o1;
                    __half h0 = __float2half(o0);
                    __half h1 = __float2half(o1);
                    __half2 hp; hp.x = h0; hp.y = h1;
                    __half2 lp;
                    lp.x = __float2half(o0 - __half2float(h0));
                    lp.y = __float2half(o1 - __half2float(h1));
                    *(__half2*)(outH + off) = hp;
                    *(__half2*)(outL + off) = lp;
                } else {
                    float2 ov = make_float2(o0, o1);
                    *(float2*)(outp + off) = ov;
                }
            }
        }
    }
}

// ---------------------------------------------------------------------------
// Chunk-parallel bidirectional WKV (3 kernels); y output = split fp16.
// ---------------------------------------------------------------------------
__global__ __launch_bounds__(256) void wkv_agg_k(
    const float* __restrict__ k, const float* __restrict__ v,
    const float* __restrict__ w,
    float* __restrict__ aFkv, float* __restrict__ aFk,
    float* __restrict__ aBkv, float* __restrict__ aBk) {
    int gid = blockIdx.x * blockDim.x + threadIdx.x;
    int c = gid & (C - 1);
    int ch = (gid >> 10) & (CH - 1);
    int b = gid >> 14;
    float d = expf(-expf(w[c]));
    size_t base = (size_t)b * T * C + (size_t)ch * CL * C + c;

    float fkv = 0.f, fk = 0.f, bkv = 0.f, bk = 0.f, pw = 1.f;
#pragma unroll 4
    for (int i = 0; i < CL; i++) {
        size_t o = base + (size_t)i * C;
        float ek = expf(k[o]);
        float kv = ek * v[o];
        fkv = fkv * d + kv;
        fk  = fk  * d + ek;
        bkv += kv * pw;
        bk  += ek * pw;
        pw *= d;
    }
    aFkv[gid] = fkv; aFk[gid] = fk;
    aBkv[gid] = bkv; aBk[gid] = bk;
}

__global__ __launch_bounds__(256) void wkv_scan_k(
    const float* __restrict__ w,
    const float* __restrict__ aFkv, const float* __restrict__ aFk,
    const float* __restrict__ aBkv, const float* __restrict__ aBk,
    float* __restrict__ iFkv, float* __restrict__ iFk,
    float* __restrict__ iBkv, float* __restrict__ iBk) {
    int gid = blockIdx.x * blockDim.x + threadIdx.x;
    int c = gid & (C - 1);
    int b = gid >> 10;
    float D = expf(-(float)CL * expf(w[c]));
    int base = b * CH * C + c;

    float skv = 0.f, sk = 0.f;
#pragma unroll
    for (int ch = 0; ch < CH; ch++) {
        int ai = base + ch * C;
        iFkv[ai] = skv; iFk[ai] = sk;
        skv = skv * D + aFkv[ai];
        sk  = sk  * D + aFk[ai];
    }
    skv = 0.f; sk = 0.f;
#pragma unroll
    for (int ch = CH - 1; ch >= 0; ch--) {
        int ai = base + ch * C;
        iBkv[ai] = skv; iBk[ai] = sk;
        skv = skv * D + aBkv[ai];
        sk  = sk  * D + aBk[ai];
    }
}

__global__ __launch_bounds__(256) void wkv_apply_k(
    const float* __restrict__ r, const float* __restrict__ k,
    const float* __restrict__ v, const float* __restrict__ w,
    const float* __restrict__ u,
    const float* __restrict__ iFkv, const float* __restrict__ iFk,
    const float* __restrict__ iBkv, const float* __restrict__ iBk,
    __half* __restrict__ y_hi, __half* __restrict__ y_lo,
    float* __restrict__ sakv, float* __restrict__ sak) {
    int gid = blockIdx.x * blockDim.x + threadIdx.x;
    int c = gid & (C - 1);
    int ch = (gid >> 10) & (CH - 1);
    int b = gid >> 14;
    float d = expf(-expf(w[c]));
    float eu = expf(u[c]);
    size_t base = (size_t)b * T * C + (size_t)ch * CL * C + c;

    float fkv = iFkv[gid], fk = iFk[gid];
#pragma unroll 4
    for (int i = 0; i < CL; i++) {
        size_t o = base + (size_t)i * C;
        float ek = expf(k[o]);
        float kv = ek * v[o];
        sakv[o] = fkv;
        sak[o]  = fk;
        fkv = fkv * d + kv;
        fk  = fk  * d + ek;
    }
    float bkv = iBkv[gid], bk = iBk[gid];
#pragma unroll 4
    for (int i = CL - 1; i >= 0; i--) {
        size_t o = base + (size_t)i * C;
        float vv = v[o];
        float ek = expf(k[o]);
        float kv = ek * vv;
        float num = sakv[o] + bkv + eu * vv;
        float den = sak[o]  + bk  + eu;
        float yv = r[o] * num / (den + 1e-8f);
        __half h = __float2half(yv);
        y_hi[o] = h;
        y_lo[o] = __float2half(yv - __half2float(h));
        bkv = bkv * d + kv;
        bk  = bk  * d + ek;
    }
}

// ---------------------------------------------------------------------------
// Host launch
// ---------------------------------------------------------------------------
extern "C" void kernel_launch(void* const* d_in, const int* in_sizes, int n_in,
                              void* d_out, int out_size) {
    const int*   idx     = (const int*)  d_in[0];
    const float* emb     = (const float*)d_in[1];
    const float* ln1_w   = (const float*)d_in[2];
    const float* ln1_b   = (const float*)d_in[3];
    const float* Wr      = (const float*)d_in[4];
    const float* Wk      = (const float*)d_in[5];
    const float* Wv      = (const float*)d_in[6];
    const float* w_decay = (const float*)d_in[7];
    const float* u_bonus = (const float*)d_in[8];
    const float* Wo      = (const float*)d_in[9];
    const float* ln2_w   = (const float*)d_in[10];
    const float* ln2_b   = (const float*)d_in[11];
    const float* Wfk     = (const float*)d_in[12];
    const float* Wfv     = (const float*)d_in[13];
    const float* Wfr     = (const float*)d_in[14];
    const float* lnout_w = (const float*)d_in[15];
    const float* lnout_b = (const float*)d_in[16];
    const float* head_W  = (const float*)d_in[17];
    float* out = (float*)d_out;

    float *x, *r, *k, *v, *sa, *sb;
    float *aFkv, *aFk, *aBkv, *aBk, *iFkv, *iFk, *iBkv, *iBk;
    __half *wt, *xnh, *xnl, *yh, *yl, *kfh, *kfl;
    cudaGetSymbolAddress((void**)&x,    g_x);
    cudaGetSymbolAddress((void**)&r,    g_r);
    cudaGetSymbolAddress((void**)&k,    g_k);
    cudaGetSymbolAddress((void**)&v,    g_v);
    cudaGetSymbolAddress((void**)&sa,   g_sakv);
    cudaGetSymbolAddress((void**)&sb,   g_sak);
    cudaGetSymbolAddress((void**)&wt,   g_wt);
    cudaGetSymbolAddress((void**)&xnh,  g_xn_hi);
    cudaGetSymbolAddress((void**)&xnl,  g_xn_lo);
    cudaGetSymbolAddress((void**)&yh,   g_y_hi);
    cudaGetSymbolAddress((void**)&yl,   g_y_lo);
    cudaGetSymbolAddress((void**)&kfh,  g_kf_hi);
    cudaGetSymbolAddress((void**)&kfl,  g_kf_lo);
    cudaGetSymbolAddress((void**)&aFkv, g_aggFkv);
    cudaGetSymbolAddress((void**)&aFk,  g_aggFk);
    cudaGetSymbolAddress((void**)&aBkv, g_aggBkv);
    cudaGetSymbolAddress((void**)&aBk,  g_aggBk);
    cudaGetSymbolAddress((void**)&iFkv, g_iniFkv);
    cudaGetSymbolAddress((void**)&iFk,  g_iniFk);
    cudaGetSymbolAddress((void**)&iBkv, g_iniBkv);
    cudaGetSymbolAddress((void**)&iBk,  g_iniBk);

    cudaFuncSetAttribute(gemm_mma<0>, cudaFuncAttributeMaxDynamicSharedMemorySize, GEMM_SMEM);
    cudaFuncSetAttribute(gemm_mma<3>, cudaFuncAttributeMaxDynamicSharedMemorySize, GEMM_SMEM);
    cudaFuncSetAttribute(gemm_mma<4>, cudaFuncAttributeMaxDynamicSharedMemorySize, GEMM_SMEM);
    cudaFuncSetAttribute(gemm_mma<5>, cudaFuncAttributeMaxDynamicSharedMemorySize, GEMM_SMEM);
    cudaFuncSetAttribute(gemm_mma<6>, cudaFuncAttributeMaxDynamicSharedMemorySize, GEMM_SMEM);

    convert_all_k<<<4096, 256>>>((const float4*)Wr, (const float4*)Wk,
                                 (const float4*)Wv, (const float4*)Wo,
                                 (const float4*)Wfr, (const float4*)Wfk,
                                 (const float4*)Wfv, (const float4*)head_W,
                                 (uint4*)wt);

    embed_k<<<M, 256>>>(idx, emb, x);

    dim3 gRKV(M / 128, 24);        // fused r/k/v     (384 CTAs)
    dim3 gCM (M / 128, 40);        // fused gate/kf   (640 CTAs)
    dim3 gCCg(M / 128, C / 128);   // 16 x 8
    dim3 gCVg(M / 128, V / 128);   // 16 x 393

    for (int l = 0; l < L; l++) {
        size_t wcc = (size_t)l * C * C;
        size_t wcf = (size_t)l * C * F;
        const float* l1w = ln1_w + (size_t)l * C;
        const float* l1b = ln1_b + (size_t)l * C;
        const float* wd  = w_decay + (size_t)l * C;
        const float* ub  = u_bonus + (size_t)l * C;
        const float* l2w = ln2_w + (size_t)l * C;
        const float* l2b = ln2_b + (size_t)l * C;

        // time-mix
        layernorm_k<<<M, 256>>>(x, l1w, l1b, xnh, xnl);
        gemm_mma<5><<<gRKV, GTHREADS, GEMM_SMEM>>>(
            xnh, xnl, wt + O_WR + wcc, nullptr,
            r, nullptr, nullptr, k, v, C, C);
        wkv_agg_k<<<(B * CH * C) / 256, 256>>>(k, v, wd, aFkv, aFk, aBkv, aBk);
        wkv_scan_k<<<(B * C) / 256, 256>>>(wd, aFkv, aFk, aBkv, aBk,
                                           iFkv, iFk, iBkv, iBk);
        wkv_apply_k<<<(B * CH * C) / 256, 256>>>(r, k, v, wd, ub,
                                                 iFkv, iFk, iBkv, iBk,
                                                 yh, yl, sa, sb);
        gemm_mma<3><<<gCCg, GTHREADS, GEMM_SMEM>>>(
            yh, yl, wt + O_WO + wcc, nullptr,
            x, nullptr, nullptr, x, nullptr, C, C);

        // channel-mix
        layernorm_k<<<M, 256>>>(x, l2w, l2b, xnh, xnl);
        gemm_mma<6><<<gCM, GTHREADS, GEMM_SMEM>>>(
            xnh, xnl, wt + O_WFR + wcc, wt + O_WFK + wcf,
            r, kfh, kfl, nullptr, nullptr, F, C);
        gemm_mma<4><<<gCCg, GTHREADS, GEMM_SMEM>>>(
            kfh, kfl, wt + O_WFV + wcf, nullptr,
            x, nullptr, nullptr, x, r, C, F);
    }

    layernorm_k<<<M, 256>>>(x, lnout_w, lnout_b, xnh, xnl);
    gemm_mma<0><<<gCVg, GTHREADS, GEMM_SMEM>>>(
        xnh, xnl, wt + O_HEAD, nullptr,
        out, nullptr, nullptr, nullptr, nullptr, V, C);
}

// round 17
// speedup vs baseline: 1.2173x; 1.0632x over previous
#include <cuda_runtime.h>
#include <cuda_bf16.h>
#include <cuda_fp16.h>
#include <cstdint>
#include <math.h>

// ---------------------------------------------------------------------------
// Problem constants
// ---------------------------------------------------------------------------
constexpr int L = 4;
constexpr int C = 1024;
constexpr int F = 4096;
constexpr int V = 50304;
constexpr int B = 2;
constexpr int T = 1024;
constexpr int M = B * T;            // 2048 rows
constexpr int CH = 16;              // wkv chunks
constexpr int CL = 64;              // wkv chunk length

// ---------------------------------------------------------------------------
// Converted-weight layout: single fp16, SAME [K,N] layout as inputs.
// ---------------------------------------------------------------------------
constexpr size_t MB1 = size_t(C) * C;         // 1,048,576
constexpr size_t O_WR   = 0;                  // [L][C][C]  (Wk = +4MB1, Wv = +8MB1)
constexpr size_t O_WK   = 4 * MB1;
constexpr size_t O_WV   = 8 * MB1;
constexpr size_t O_WO   = 12 * MB1;
constexpr size_t O_WFR  = 16 * MB1;
constexpr size_t O_WFK  = 20 * MB1;           // [L][C][F]
constexpr size_t O_WFV  = 36 * MB1;           // [L][F][C]
constexpr size_t O_HEAD = 52 * MB1;           // [C][V]
constexpr size_t WTOTAL = O_HEAD + size_t(V) * C;

__device__ alignas(16) __half g_wt[WTOTAL];

__device__ alignas(16) float g_x   [size_t(M) * C];
__device__ alignas(16) float g_r   [size_t(M) * C];
__device__ alignas(16) float g_k   [size_t(M) * C];
__device__ alignas(16) float g_v   [size_t(M) * C];
__device__ alignas(16) float g_sakv[size_t(M) * C];
__device__ alignas(16) float g_sak [size_t(M) * C];
__device__ alignas(16) __half g_xn_hi[size_t(M) * C];
__device__ alignas(16) __half g_xn_lo[size_t(M) * C];
__device__ alignas(16) __half g_y_hi [size_t(M) * C];
__device__ alignas(16) __half g_y_lo [size_t(M) * C];
__device__ alignas(16) __half g_kf_hi[size_t(M) * F];
__device__ alignas(16) __half g_kf_lo[size_t(M) * F];

// wkv chunk-scan scratch: [B][CH][C]
constexpr int AGG = B * CH * C;    // 32768
__device__ alignas(16) float g_aggFkv[AGG];
__device__ alignas(16) float g_aggFk [AGG];
__device__ alignas(16) float g_aggBkv[AGG];
__device__ alignas(16) float g_aggBk [AGG];
__device__ alignas(16) float g_iniFkv[AGG];
__device__ alignas(16) float g_iniFk [AGG];
__device__ alignas(16) float g_iniBkv[AGG];
__device__ alignas(16) float g_iniBk [AGG];

// ---------------------------------------------------------------------------
// Merged streaming conversion: fp32 -> single fp16, 16B stores.
// ---------------------------------------------------------------------------
constexpr size_t N4_CC = size_t(L) * C * C / 4;
constexpr size_t N4_CF = size_t(L) * C * F / 4;
constexpr size_t N4_HD = size_t(V) * C / 4;
constexpr size_t CV_B0 = N4_CC;
constexpr size_t CV_B1 = CV_B0 + N4_CC;
constexpr size_t CV_B2 = CV_B1 + N4_CC;
constexpr size_t CV_B3 = CV_B2 + N4_CC;
constexpr size_t CV_B4 = CV_B3 + N4_CC;
constexpr size_t CV_B5 = CV_B4 + N4_CF;
constexpr size_t CV_B6 = CV_B5 + N4_CF;
constexpr size_t CV_TOT = CV_B6 + N4_HD;
constexpr size_t CV_G = CV_TOT / 2;           // groups of 2 float4 (8 floats)

__device__ __forceinline__ uint32_t pack_h2(float a, float b) {
    __half2 h;
    h.x = __float2half(a);
    h.y = __float2half(b);
    return *(uint32_t*)&h;
}

__global__ __launch_bounds__(256) void convert_all_k(
    const float4* __restrict__ wr, const float4* __restrict__ wk,
    const float4* __restrict__ wv, const float4* __restrict__ wo,
    const float4* __restrict__ wfr, const float4* __restrict__ wfk,
    const float4* __restrict__ wfv, const float4* __restrict__ hd,
    uint4* __restrict__ oh) {
    size_t stride = (size_t)gridDim.x * blockDim.x;
    for (size_t g = (size_t)blockIdx.x * blockDim.x + threadIdx.x; g < CV_G;
         g += stride) {
        size_t i = 2 * g;
        const float4* src;
        size_t dstg;   // uint4 index (8 halves)
        if (i < CV_B0)      { src = wr  + i;            dstg = O_WR  / 8 + g; }
        else if (i < CV_B1) { src = wk  + (i - CV_B0);  dstg = O_WK  / 8 + (g - CV_B0 / 2); }
        else if (i < CV_B2) { src = wv  + (i - CV_B1);  dstg = O_WV  / 8 + (g - CV_B1 / 2); }
        else if (i < CV_B3) { src = wo  + (i - CV_B2);  dstg = O_WO  / 8 + (g - CV_B2 / 2); }
        else if (i < CV_B4) { src = wfr + (i - CV_B3);  dstg = O_WFR / 8 + (g - CV_B3 / 2); }
        else if (i < CV_B5) { src = wfk + (i - CV_B4);  dstg = O_WFK / 8 + (g - CV_B4 / 2); }
        else if (i < CV_B6) { src = wfv + (i - CV_B5);  dstg = O_WFV / 8 + (g - CV_B5 / 2); }
        else                { src = hd  + (i - CV_B6);  dstg = O_HEAD/ 8 + (g - CV_B6 / 2); }
        float4 w0 = src[0];
        float4 w1 = src[1];
        uint4 H;
        H.x = pack_h2(w0.x, w0.y);
        H.y = pack_h2(w0.z, w0.w);
        H.z = pack_h2(w1.x, w1.y);
        H.w = pack_h2(w1.z, w1.w);
        oh[dstg] = H;
    }
}

// ---------------------------------------------------------------------------
// Embedding gather
// ---------------------------------------------------------------------------
__global__ void embed_k(const int* __restrict__ idx,
                        const float* __restrict__ emb,
                        float* __restrict__ x) {
    int row = blockIdx.x;
    int id = idx[row];
    const float4* src = (const float4*)(emb + (size_t)id * C);
    float4* dst = (float4*)(x + (size_t)row * C);
    for (int i = threadIdx.x; i < C / 4; i += blockDim.x) dst[i] = src[i];
}

// ---------------------------------------------------------------------------
// LayerNorm -> split fp16 output (hi + residual lo)
// ---------------------------------------------------------------------------
__global__ __launch_bounds__(256) void layernorm_k(const float* __restrict__ x,
                                                   const float* __restrict__ w,
                                                   const float* __restrict__ b,
                                                   __half* __restrict__ out_hi,
                                                   __half* __restrict__ out_lo) {
    __shared__ float red[256];
    int row = blockIdx.x;
    const float* xr = x + (size_t)row * C;
    float v[4];
    float s = 0.f;
#pragma unroll
    for (int i = 0; i < 4; i++) { v[i] = xr[threadIdx.x + 256 * i]; s += v[i]; }
    red[threadIdx.x] = s;
    __syncthreads();
    for (int o = 128; o > 0; o >>= 1) {
        if (threadIdx.x < o) red[threadIdx.x] += red[threadIdx.x + o];
        __syncthreads();
    }
    float mu = red[0] * (1.f / C);
    __syncthreads();
    float s2 = 0.f;
#pragma unroll
    for (int i = 0; i < 4; i++) { float d = v[i] - mu; s2 += d * d; }
    red[threadIdx.x] = s2;
    __syncthreads();
    for (int o = 128; o > 0; o >>= 1) {
        if (threadIdx.x < o) red[threadIdx.x] += red[threadIdx.x + o];
        __syncthreads();
    }
    float rstd = rsqrtf(red[0] * (1.f / C) + 1e-5f);
#pragma unroll
    for (int i = 0; i < 4; i++) {
        int c = threadIdx.x + 256 * i;
        float o = (v[i] - mu) * rstd * w[c] + b[c];
        __half h = __float2half(o);
        size_t off = (size_t)row * C + c;
        out_hi[off] = h;
        out_lo[off] = __float2half(o - __half2float(h));
    }
}

// ---------------------------------------------------------------------------
// Shared GEMM building blocks (fp16 split-A, 2 terms: Ah*B + Al*B)
// ---------------------------------------------------------------------------
constexpr int BK = 32;
constexpr int SSTRA = 40;                     // A row pad (80B)
constexpr int SSTRB = 136;                    // B row pad (272B)
constexpr int TA = 128 * SSTRA * 2;           // 10240 B
constexpr int TB = BK * SSTRB * 2;            // 8704 B
constexpr int OFF_AH = 0;
constexpr int OFF_AL = TA;
constexpr int OFF_B  = 2 * TA;
constexpr int STAGEB = 2 * TA + TB;           // 29184 B

// 512-thread / 6-stage variant (used for the 128-CTA grids: Wo, Wfv)
constexpr int NSTAGE = 6;
constexpr int GEMM_SMEM = NSTAGE * STAGEB;    // 175104 B
constexpr int GTHREADS = 512;

// 256-thread / 3-stage / 2-CTA-per-SM variant (rkv, gate/kf, head)
constexpr int NSTAGE2 = 3;
constexpr int GEMM2_SMEM = NSTAGE2 * STAGEB;  // 87552 B

__device__ __forceinline__ uint32_t smem_u32(const void* p) {
    uint32_t a;
    asm("{ .reg .u64 t; cvta.to.shared.u64 t, %1; cvt.u32.u64 %0, t; }"
        : "=r"(a) : "l"(p));
    return a;
}

__device__ __forceinline__ void ldsm_x4(uint32_t addr, uint32_t& r0, uint32_t& r1,
                                        uint32_t& r2, uint32_t& r3) {
    asm volatile("ldmatrix.sync.aligned.m8n8.x4.shared.b16 {%0,%1,%2,%3}, [%4];"
                 : "=r"(r0), "=r"(r1), "=r"(r2), "=r"(r3) : "r"(addr));
}

__device__ __forceinline__ void ldsm_x4_t(uint32_t addr, uint32_t& r0, uint32_t& r1,
                                          uint32_t& r2, uint32_t& r3) {
    asm volatile("ldmatrix.sync.aligned.m8n8.x4.trans.shared.b16 {%0,%1,%2,%3}, [%4];"
                 : "=r"(r0), "=r"(r1), "=r"(r2), "=r"(r3) : "r"(addr));
}

__device__ __forceinline__ void mma_f16(float* d, const uint32_t* a,
                                        uint32_t b0, uint32_t b1) {
    asm volatile(
        "mma.sync.aligned.m16n8k16.row.col.f32.f16.f16.f32 "
        "{%0,%1,%2,%3}, {%4,%5,%6,%7}, {%8,%9}, {%0,%1,%2,%3};"
        : "+f"(d[0]), "+f"(d[1]), "+f"(d[2]), "+f"(d[3])
        : "r"(a[0]), "r"(a[1]), "r"(a[2]), "r"(a[3]), "r"(b0), "r"(b1));
}

__device__ __forceinline__ void cp16(uint32_t sp, const void* gp) {
    asm volatile("cp.async.cg.shared.global [%0], [%1], 16;" :: "r"(sp), "l"(gp));
}

// A tile: 128 rows x 32 k (64B/row). 128 threads: 1 row, 4 cp16 each.
__device__ __forceinline__ void issue_A(uint32_t dst, const __half* __restrict__ g,
                                        int brow, int K, int k0, int t128) {
    int r = t128;
    const __half* gp = g + (size_t)(brow + r) * K + k0;
    uint32_t sp = dst + r * (SSTRA * 2);
#pragma unroll
    for (int cc = 0; cc < 4; cc++)
        cp16(sp + cc * 16, gp + cc * 8);
}

// B tile: 32 k-rows x 128 n. 256 threads: 2 chunks each.
__device__ __forceinline__ void issue_B(uint32_t dst, const __half* __restrict__ g,
                                        int bcol, int Nb, int k0, int q256) {
    int r = q256 >> 3;               // 0..31
    int c0 = (q256 & 7) * 2;         // chunk index 0..14 step 2
    const __half* gp = g + (size_t)(k0 + r) * Nb + bcol + c0 * 8;
    uint32_t sp = dst + r * (SSTRB * 2) + c0 * 16;
#pragma unroll
    for (int cc = 0; cc < 2; cc++)
        cp16(sp + cc * 16, gp + cc * 8);
}

// ---------------------------------------------------------------------------
// 512-thread GEMM (proven round-13 core) — MODE 3 (res+acc) / 4 (res+gate*acc).
// ---------------------------------------------------------------------------
template <int MODE>
__global__ __launch_bounds__(GTHREADS, 1) void gemm_mma(
    const __half* __restrict__ Ah, const __half* __restrict__ Al,
    const __half* __restrict__ Bw,
    float* __restrict__ out0,
    const float* __restrict__ res, const float* __restrict__ gate,
    int N, int K) {
    extern __shared__ __align__(128) char sm[];
    uint32_t smem = smem_u32(sm);
    int tid = threadIdx.x;
    int wid = tid >> 5;
    int lane = tid & 31;
    int brow = blockIdx.x * 128;
    int bcol = blockIdx.y * 128;

    int warp_m = wid & 3;
    int warp_n = wid >> 2;
    int t128 = tid & 127;
    int q256 = tid - 256;

    float acc[2][4][4];
#pragma unroll
    for (int i = 0; i < 2; i++)
#pragma unroll
        for (int j = 0; j < 4; j++)
#pragma unroll
            for (int q = 0; q < 4; q++) acc[i][j][q] = 0.f;

    int nch = K >> 5;

#pragma unroll
    for (int s = 0; s < NSTAGE - 1; s++) {
        uint32_t sb = smem + s * STAGEB;
        if (tid < 128)       issue_A(sb + OFF_AH, Ah, brow, K, s * BK, t128);
        else if (tid < 256)  issue_A(sb + OFF_AL, Al, brow, K, s * BK, t128);
        else                 issue_B(sb + OFF_B,  Bw, bcol, N, s * BK, q256);
        asm volatile("cp.async.commit_group;");
    }

    int a_r = (lane & 15);
    int a_k = ((lane >> 4) << 3);
    int b_kr = (lane & 15);
    int b_nf = ((lane >> 4) << 3);

    uint32_t aoffw = (uint32_t)(warp_m * 32 + a_r) * (SSTRA * 2) + a_k * 2;
    uint32_t boffw = (uint32_t)b_kr * (SSTRB * 2) + (warp_n * 32 + b_nf) * 2;
    constexpr uint32_t DAM = 16 * (SSTRA * 2);
    constexpr uint32_t DBN = 16 * 2;
    constexpr uint32_t DAK = 32;
    constexpr uint32_t DBK = 16 * (SSTRB * 2);

    asm volatile("cp.async.wait_group 4;");
    __syncthreads();

    uint32_t ahc[2][4], bhc[4][2];
    {
        uint32_t aA0 = smem + OFF_AH + aoffw;
        uint32_t bB0 = smem + OFF_B + boffw;
        ldsm_x4(aA0,       ahc[0][0], ahc[0][1], ahc[0][2], ahc[0][3]);
        ldsm_x4(aA0 + DAM, ahc[1][0], ahc[1][1], ahc[1][2], ahc[1][3]);
        uint32_t r0, r1, r2, r3;
        ldsm_x4_t(bB0,       r0, r1, r2, r3);
        bhc[0][0] = r0; bhc[0][1] = r1; bhc[1][0] = r2; bhc[1][1] = r3;
        ldsm_x4_t(bB0 + DBN, r0, r1, r2, r3);
        bhc[2][0] = r0; bhc[2][1] = r1; bhc[3][0] = r2; bhc[3][1] = r3;
    }

#pragma unroll 1
    for (int c = 0; c < nch; c++) {
        uint32_t sbase = smem + (c % NSTAGE) * STAGEB;
        uint32_t aA0 = sbase + OFF_AH + aoffw;
        uint32_t bB0 = sbase + OFF_B + boffw;

        uint32_t al[2][4], ah1[2][4], bh1[4][2];

#pragma unroll
        for (int mi = 0; mi < 2; mi++)
#pragma unroll
            for (int ni = 0; ni < 4; ni++)
                mma_f16(acc[mi][ni], ahc[mi], bhc[ni][0], bhc[ni][1]);

        ldsm_x4(aA0 + TA,       al[0][0], al[0][1], al[0][2], al[0][3]);
        ldsm_x4(aA0 + TA + DAM, al[1][0], al[1][1], al[1][2], al[1][3]);

#pragma unroll
        for (int mi = 0; mi < 2; mi++)
#pragma unroll
            for (int ni = 0; ni < 4; ni++)
                mma_f16(acc[mi][ni], al[mi], bhc[ni][0], bhc[ni][1]);

        ldsm_x4(aA0 + DAK,       ah1[0][0], ah1[0][1], ah1[0][2], ah1[0][3]);
        ldsm_x4(aA0 + DAK + DAM, ah1[1][0], ah1[1][1], ah1[1][2], ah1[1][3]);
        {
            uint32_t r0, r1, r2, r3;
            ldsm_x4_t(bB0 + DBK,       r0, r1, r2, r3);
            bh1[0][0] = r0; bh1[0][1] = r1; bh1[1][0] = r2; bh1[1][1] = r3;
            ldsm_x4_t(bB0 + DBK + DBN, r0, r1, r2, r3);
            bh1[2][0] = r0; bh1[2][1] = r1; bh1[3][0] = r2; bh1[3][1] = r3;
        }

        if (c + NSTAGE - 1 < nch) {
            uint32_t sb = smem + ((c + NSTAGE - 1) % NSTAGE) * STAGEB;
            int k0 = (c + NSTAGE - 1) * BK;
            if (tid < 128)       issue_A(sb + OFF_AH, Ah, brow, K, k0, t128);
            else if (tid < 256)  issue_A(sb + OFF_AL, Al, brow, K, k0, t128);
            else                 issue_B(sb + OFF_B,  Bw, bcol, N, k0, q256);
        }
        asm volatile("cp.async.commit_group;");

#pragma unroll
        for (int mi = 0; mi < 2; mi++)
#pragma unroll
            for (int ni = 0; ni < 4; ni++)
                mma_f16(acc[mi][ni], ah1[mi], bh1[ni][0], bh1[ni][1]);

        ldsm_x4(aA0 + DAK + TA,       al[0][0], al[0][1], al[0][2], al[0][3]);
        ldsm_x4(aA0 + DAK + TA + DAM, al[1][0], al[1][1], al[1][2], al[1][3]);

        asm volatile("cp.async.wait_group 4;");
        if (c + 1 < nch) {
            uint32_t sbn = smem + ((c + 1) % NSTAGE) * STAGEB;
            uint32_t aN = sbn + OFF_AH + aoffw;
            uint32_t bN = sbn + OFF_B + boffw;
            ldsm_x4(aN,       ahc[0][0], ahc[0][1], ahc[0][2], ahc[0][3]);
            ldsm_x4(aN + DAM, ahc[1][0], ahc[1][1], ahc[1][2], ahc[1][3]);
            uint32_t r0, r1, r2, r3;
            ldsm_x4_t(bN,       r0, r1, r2, r3);
            bhc[0][0] = r0; bhc[0][1] = r1; bhc[1][0] = r2; bhc[1][1] = r3;
            ldsm_x4_t(bN + DBN, r0, r1, r2, r3);
            bhc[2][0] = r0; bhc[2][1] = r1; bhc[3][0] = r2; bhc[3][1] = r3;
        }

        __syncthreads();

#pragma unroll
        for (int mi = 0; mi < 2; mi++)
#pragma unroll
            for (int ni = 0; ni < 4; ni++)
                mma_f16(acc[mi][ni], al[mi], bh1[ni][0], bh1[ni][1]);
    }

    // epilogue (MODE 3 / 4)
    int qrow = lane >> 2;
    int qcol = (lane & 3) * 2;
#pragma unroll
    for (int mi = 0; mi < 2; mi++) {
#pragma unroll
        for (int h = 0; h < 2; h++) {
            int row = brow + warp_m * 32 + mi * 16 + qrow + h * 8;
#pragma unroll
            for (int ni = 0; ni < 4; ni++) {
                int col = bcol + warp_n * 32 + ni * 8 + qcol;
                size_t off = (size_t)row * N + col;
                float o0 = acc[mi][ni][h * 2];
                float o1 = acc[mi][ni][h * 2 + 1];
                if (MODE == 3) {
                    const float2 rv = *(const float2*)(res + off);
                    o0 += rv.x; o1 += rv.y;
                } else {
                    const float2 rv = *(const float2*)(res + off);
                    const float2 gv = *(const float2*)(gate + off);
                    o0 = rv.x + gv.x * o0;
                    o1 = rv.y + gv.y * o1;
                }
                float2 ov = make_float2(o0, o1);
                *(float2*)(out0 + off) = ov;
            }
        }
    }
}

// ---------------------------------------------------------------------------
// 256-thread / 2-CTA-per-SM GEMM — 128x128 tile, 8 warps (warp 64x32),
// NSTAGE2=3.  Preload of next chunk's B fragments now AFTER __syncthreads
// (wait_group is per-thread; cross-thread cp.async visibility needs the
// barrier first).  Tail lh1 MMAs are register-resident and cover the LDSMs.
// MODE 0 plain | MODE 5 fused r/k/v | MODE 6 fused gate(N=C)/kf(N=F)
// ---------------------------------------------------------------------------
template <int MODE>
__global__ __launch_bounds__(256, 2) void gemm_mma2(
    const __half* __restrict__ Ah, const __half* __restrict__ Al,
    const __half* __restrict__ Bw, const __half* __restrict__ Bw2,
    float* __restrict__ out0,
    __half* __restrict__ outH, __half* __restrict__ outL,
    const float* __restrict__ res, const float* __restrict__ gate,
    int N, int K) {
    extern __shared__ __align__(128) char sm[];
    uint32_t smem = smem_u32(sm);
    int tid = threadIdx.x;
    int wid = tid >> 5;
    int lane = tid & 31;
    int brow = blockIdx.x * 128;

    // mode-dependent B / output routing
    int bcol, Nb, Nout, epi;
    const __half* BS;
    float* outp = out0;
    if (MODE == 5) {
        int sel = blockIdx.y >> 3;
        bcol = (blockIdx.y & 7) * 128;
        BS = Bw + (size_t)sel * 4 * MB1;
        Nb = N; Nout = N;
        epi = (sel == 0) ? 1 : 0;
        outp = (sel == 0) ? out0 : (sel == 1 ? const_cast<float*>(res)
                                             : const_cast<float*>(gate));
    } else if (MODE == 6) {
        if (blockIdx.y < 8) {
            bcol = blockIdx.y * 128;
            BS = Bw;
            Nb = C; Nout = C;
            epi = 1;
        } else {
            bcol = (blockIdx.y - 8) * 128;
            BS = Bw2;
            Nb = N; Nout = N;          // N = F
            epi = 2;
        }
    } else {
        bcol = blockIdx.y * 128;
        BS = Bw;
        Nb = N; Nout = N;
        epi = 0;
    }

    int warp_m = wid & 1;          // 0..1 (64 rows each)
    int warp_n = wid >> 1;         // 0..3 (32 cols each)
    int t128 = tid & 127;

    float acc[4][4][4];            // [mi][ni][4]
#pragma unroll
    for (int i = 0; i < 4; i++)
#pragma unroll
        for (int j = 0; j < 4; j++)
#pragma unroll
            for (int q = 0; q < 4; q++) acc[i][j][q] = 0.f;

    int nch = K >> 5;

    // prologue: stages 0,1 (A by halves; B by all 256)
#pragma unroll
    for (int s = 0; s < NSTAGE2 - 1; s++) {
        uint32_t sb = smem + s * STAGEB;
        if (tid < 128) issue_A(sb + OFF_AH, Ah, brow, K, s * BK, t128);
        else           issue_A(sb + OFF_AL, Al, brow, K, s * BK, t128);
        issue_B(sb + OFF_B, BS, bcol, Nb, s * BK, tid);
        asm volatile("cp.async.commit_group;");
    }

    int a_r = (lane & 15);
    int a_k = ((lane >> 4) << 3);
    int b_kr = (lane & 15);
    int b_nf = ((lane >> 4) << 3);

    uint32_t aoffw = (uint32_t)(warp_m * 64 + a_r) * (SSTRA * 2) + a_k * 2;
    uint32_t boffw = (uint32_t)b_kr * (SSTRB * 2) + (warp_n * 32 + b_nf) * 2;
    constexpr uint32_t DAM = 16 * (SSTRA * 2);
    constexpr uint32_t DBN = 16 * 2;
    constexpr uint32_t DAK = 32;
    constexpr uint32_t DBK = 16 * (SSTRB * 2);

    // stage 0 ready (wait + barrier), THEN preload chunk-0 ks0 B fragments
    asm volatile("cp.async.wait_group 1;");
    __syncthreads();

    uint32_t bhc[4][2];            // persistent ks0 B of current chunk
    {
        uint32_t bB0 = smem + OFF_B + boffw;
        uint32_t r0, r1, r2, r3;
        ldsm_x4_t(bB0,       r0, r1, r2, r3);
        bhc[0][0] = r0; bhc[0][1] = r1; bhc[1][0] = r2; bhc[1][1] = r3;
        ldsm_x4_t(bB0 + DBN, r0, r1, r2, r3);
        bhc[2][0] = r0; bhc[2][1] = r1; bhc[3][0] = r2; bhc[3][1] = r3;
    }

#pragma unroll 1
    for (int c = 0; c < nch; c++) {
        uint32_t sbase = smem + (c % NSTAGE2) * STAGEB;
        uint32_t aA0 = sbase + OFF_AH + aoffw;
        uint32_t bB0 = sbase + OFF_B + boffw;

        uint32_t a[4][4], bh1[4][2];

        // ks0 A-hi + hh0
#pragma unroll
        for (int mi = 0; mi < 4; mi++)
            ldsm_x4(aA0 + mi * DAM, a[mi][0], a[mi][1], a[mi][2], a[mi][3]);
#pragma unroll
        for (int mi = 0; mi < 4; mi++)
#pragma unroll
            for (int ni = 0; ni < 4; ni++)
                mma_f16(acc[mi][ni], a[mi], bhc[ni][0], bhc[ni][1]);

        // ks0 A-lo + lh0 (reuse buffer a)
#pragma unroll
        for (int mi = 0; mi < 4; mi++)
            ldsm_x4(aA0 + TA + mi * DAM, a[mi][0], a[mi][1], a[mi][2], a[mi][3]);
#pragma unroll
        for (int mi = 0; mi < 4; mi++)
#pragma unroll
            for (int ni = 0; ni < 4; ni++)
                mma_f16(acc[mi][ni], a[mi], bhc[ni][0], bhc[ni][1]);

        // ks1 B
        {
            uint32_t r0, r1, r2, r3;
            ldsm_x4_t(bB0 + DBK,       r0, r1, r2, r3);
            bh1[0][0] = r0; bh1[0][1] = r1; bh1[1][0] = r2; bh1[1][1] = r3;
            ldsm_x4_t(bB0 + DBK + DBN, r0, r1, r2, r3);
            bh1[2][0] = r0; bh1[2][1] = r1; bh1[3][0] = r2; bh1[3][1] = r3;
        }
        // ks1 A-hi
#pragma unroll
        for (int mi = 0; mi < 4; mi++)
            ldsm_x4(aA0 + DAK + mi * DAM, a[mi][0], a[mi][1], a[mi][2], a[mi][3]);

        // global prefetch for stage c+2 (one commit per chunk)
        if (c + NSTAGE2 - 1 < nch) {
            uint32_t sb = smem + ((c + NSTAGE2 - 1) % NSTAGE2) * STAGEB;
            int k0 = (c + NSTAGE2 - 1) * BK;
            if (tid < 128) issue_A(sb + OFF_AH, Ah, brow, K, k0, t128);
            else           issue_A(sb + OFF_AL, Al, brow, K, k0, t128);
            issue_B(sb + OFF_B, BS, bcol, Nb, k0, tid);
        }
        asm volatile("cp.async.commit_group;");

        // hh1
#pragma unroll
        for (int mi = 0; mi < 4; mi++)
#pragma unroll
            for (int ni = 0; ni < 4; ni++)
                mma_f16(acc[mi][ni], a[mi], bh1[ni][0], bh1[ni][1]);

        // ks1 A-lo
#pragma unroll
        for (int mi = 0; mi < 4; mi++)
            ldsm_x4(aA0 + DAK + TA + mi * DAM, a[mi][0], a[mi][1], a[mi][2], a[mi][3]);

        // drain, then BARRIER (cross-thread cp.async visibility), THEN preload
        asm volatile("cp.async.wait_group 1;");
        __syncthreads();
        if (c + 1 < nch) {
            uint32_t bN = smem + ((c + 1) % NSTAGE2) * STAGEB + OFF_B + boffw;
            uint32_t r0, r1, r2, r3;
            ldsm_x4_t(bN,       r0, r1, r2, r3);
            bhc[0][0] = r0; bhc[0][1] = r1; bhc[1][0] = r2; bhc[1][1] = r3;
            ldsm_x4_t(bN + DBN, r0, r1, r2, r3);
            bhc[2][0] = r0; bhc[2][1] = r1; bhc[3][0] = r2; bhc[3][1] = r3;
        }

        // tail lh1 MMAs (register-resident; cover the preload LDSMs)
#pragma unroll
        for (int mi = 0; mi < 4; mi++)
#pragma unroll
            for (int ni = 0; ni < 4; ni++)
                mma_f16(acc[mi][ni], a[mi], bh1[ni][0], bh1[ni][1]);
    }

    // ---- epilogue ----
    int qrow = lane >> 2;
    int qcol = (lane & 3) * 2;
#pragma unroll
    for (int mi = 0; mi < 4; mi++) {
#pragma unroll
        for (int h = 0; h < 2; h++) {
            int row = brow + warp_m * 64 + mi * 16 + qrow + h * 8;
#pragma unroll
            for (int ni = 0; ni < 4; ni++) {
                int col = bcol + warp_n * 32 + ni * 8 + qcol;
                size_t off = (size_t)row * Nout + col;
                float o0 = acc[mi][ni][h * 2];
                float o1 = acc[mi][ni][h * 2 + 1];
                if (epi == 1) {
                    o0 = 1.f / (1.f + expf(-o0));
                    o1 = 1.f / (1.f + expf(-o1));
                }
                if (epi == 2) {
                    o0 = fmaxf(o0, 0.f); o0 *= o0;
                    o1 = fmaxf(o1, 0.f); o1 *= o1;
                    __half h0 = __float2half(o0);
                    __half h1 = __float2half(o1);
                    __half2 hp; hp.x = h0; hp.y = h1;
                    __half2 lp;
                    lp.x = __float2half(o0 - __half2float(h0));
                    lp.y = __float2half(o1 - __half2float(h1));
                    *(__half2*)(outH + off) = hp;
                    *(__half2*)(outL + off) = lp;
                } else {
                    float2 ov = make_float2(o0, o1);
                    *(float2*)(outp + off) = ov;
                }
            }
        }
    }
}

// ---------------------------------------------------------------------------
// Chunk-parallel bidirectional WKV (3 kernels); y output = split fp16.
// ---------------------------------------------------------------------------
__global__ __launch_bounds__(256) void wkv_agg_k(
    const float* __restrict__ k, const float* __restrict__ v,
    const float* __restrict__ w,
    float* __restrict__ aFkv, float* __restrict__ aFk,
    float* __restrict__ aBkv, float* __restrict__ aBk) {
    int gid = blockIdx.x * blockDim.x + threadIdx.x;
    int c = gid & (C - 1);
    int ch = (gid >> 10) & (CH - 1);
    int b = gid >> 14;
    float d = expf(-expf(w[c]));
    size_t base = (size_t)b * T * C + (size_t)ch * CL * C + c;

    float fkv = 0.f, fk = 0.f, bkv = 0.f, bk = 0.f, pw = 1.f;
#pragma unroll 4
    for (int i = 0; i < CL; i++) {
        size_t o = base + (size_t)i * C;
        float ek = expf(k[o]);
        float kv = ek * v[o];
        fkv = fkv * d + kv;
        fk  = fk  * d + ek;
        bkv += kv * pw;
        bk  += ek * pw;
        pw *= d;
    }
    aFkv[gid] = fkv; aFk[gid] = fk;
    aBkv[gid] = bkv; aBk[gid] = bk;
}

__global__ __launch_bounds__(256) void wkv_scan_k(
    const float* __restrict__ w,
    const float* __restrict__ aFkv, const float* __restrict__ aFk,
    const float* __restrict__ aBkv, const float* __restrict__ aBk,
    float* __restrict__ iFkv, float* __restrict__ iFk,
    float* __restrict__ iBkv, float* __restrict__ iBk) {
    int gid = blockIdx.x * blockDim.x + threadIdx.x;
    int c = gid & (C - 1);
    int b = gid >> 10;
    float D = expf(-(float)CL * expf(w[c]));
    int base = b * CH * C + c;

    float skv = 0.f, sk = 0.f;
#pragma unroll
    for (int ch = 0; ch < CH; ch++) {
        int ai = base + ch * C;
        iFkv[ai] = skv; iFk[ai] = sk;
        skv = skv * D + aFkv[ai];
        sk  = sk  * D + aFk[ai];
    }
    skv = 0.f; sk = 0.f;
#pragma unroll
    for (int ch = CH - 1; ch >= 0; ch--) {
        int ai = base + ch * C;
        iBkv[ai] = skv; iBk[ai] = sk;
        skv = skv * D + aBkv[ai];
        sk  = sk  * D + aBk[ai];
    }
}

__global__ __launch_bounds__(256) void wkv_apply_k(
    const float* __restrict__ r, const float* __restrict__ k,
    const float* __restrict__ v, const float* __restrict__ w,
    const float* __restrict__ u,
    const float* __restrict__ iFkv, const float* __restrict__ iFk,
    const float* __restrict__ iBkv, const float* __restrict__ iBk,
    __half* __restrict__ y_hi, __half* __restrict__ y_lo,
    float* __restrict__ sakv, float* __restrict__ sak) {
    int gid = blockIdx.x * blockDim.x + threadIdx.x;
    int c = gid & (C - 1);
    int ch = (gid >> 10) & (CH - 1);
    int b = gid >> 14;
    float d = expf(-expf(w[c]));
    float eu = expf(u[c]);
    size_t base = (size_t)b * T * C + (size_t)ch * CL * C + c;

    float fkv = iFkv[gid], fk = iFk[gid];
#pragma unroll 4
    for (int i = 0; i < CL; i++) {
        size_t o = base + (size_t)i * C;
        float ek = expf(k[o]);
        float kv = ek * v[o];
        sakv[o] = fkv;
        sak[o]  = fk;
        fkv = fkv * d + kv;
        fk  = fk  * d + ek;
    }
    float bkv = iBkv[gid], bk = iBk[gid];
#pragma unroll 4
    for (int i = CL - 1; i >= 0; i--) {
        size_t o = base + (size_t)i * C;
        float vv = v[o];
        float ek = expf(k[o]);
        float kv = ek * vv;
        float num = sakv[o] + bkv + eu * vv;
        float den = sak[o]  + bk  + eu;
        float yv = r[o] * num / (den + 1e-8f);
        __half h = __float2half(yv);
        y_hi[o] = h;
        y_lo[o] = __float2half(yv - __half2float(h));
        bkv = bkv * d + kv;
        bk  = bk  * d + ek;
    }
}

// ---------------------------------------------------------------------------
// Host launch
// ---------------------------------------------------------------------------
extern "C" void kernel_launch(void* const* d_in, const int* in_sizes, int n_in,
                              void* d_out, int out_size) {
    const int*   idx     = (const int*)  d_in[0];
    const float* emb     = (const float*)d_in[1];
    const float* ln1_w   = (const float*)d_in[2];
    const float* ln1_b   = (const float*)d_in[3];
    const float* Wr      = (const float*)d_in[4];
    const float* Wk      = (const float*)d_in[5];
    const float* Wv      = (const float*)d_in[6];
    const float* w_decay = (const float*)d_in[7];
    const float* u_bonus = (const float*)d_in[8];
    const float* Wo      = (const float*)d_in[9];
    const float* ln2_w   = (const float*)d_in[10];
    const float* ln2_b   = (const float*)d_in[11];
    const float* Wfk     = (const float*)d_in[12];
    const float* Wfv     = (const float*)d_in[13];
    const float* Wfr     = (const float*)d_in[14];
    const float* lnout_w = (const float*)d_in[15];
    const float* lnout_b = (const float*)d_in[16];
    const float* head_W  = (const float*)d_in[17];
    float* out = (float*)d_out;

    float *x, *r, *k, *v, *sa, *sb;
    float *aFkv, *aFk, *aBkv, *aBk, *iFkv, *iFk, *iBkv, *iBk;
    __half *wt, *xnh, *xnl, *yh, *yl, *kfh, *kfl;
    cudaGetSymbolAddress((void**)&x,    g_x);
    cudaGetSymbolAddress((void**)&r,    g_r);
    cudaGetSymbolAddress((void**)&k,    g_k);
    cudaGetSymbolAddress((void**)&v,    g_v);
    cudaGetSymbolAddress((void**)&sa,   g_sakv);
    cudaGetSymbolAddress((void**)&sb,   g_sak);
    cudaGetSymbolAddress((void**)&wt,   g_wt);
    cudaGetSymbolAddress((void**)&xnh,  g_xn_hi);
    cudaGetSymbolAddress((void**)&xnl,  g_xn_lo);
    cudaGetSymbolAddress((void**)&yh,   g_y_hi);
    cudaGetSymbolAddress((void**)&yl,   g_y_lo);
    cudaGetSymbolAddress((void**)&kfh,  g_kf_hi);
    cudaGetSymbolAddress((void**)&kfl,  g_kf_lo);
    cudaGetSymbolAddress((void**)&aFkv, g_aggFkv);
    cudaGetSymbolAddress((void**)&aFk,  g_aggFk);
    cudaGetSymbolAddress((void**)&aBkv, g_aggBkv);
    cudaGetSymbolAddress((void**)&aBk,  g_aggBk);
    cudaGetSymbolAddress((void**)&iFkv, g_iniFkv);
    cudaGetSymbolAddress((void**)&iFk,  g_iniFk);
    cudaGetSymbolAddress((void**)&iBkv, g_iniBkv);
    cudaGetSymbolAddress((void**)&iBk,  g_iniBk);

    cudaFuncSetAttribute(gemm_mma<3>, cudaFuncAttributeMaxDynamicSharedMemorySize, GEMM_SMEM);
    cudaFuncSetAttribute(gemm_mma<4>, cudaFuncAttributeMaxDynamicSharedMemorySize, GEMM_SMEM);
    cudaFuncSetAttribute(gemm_mma2<0>, cudaFuncAttributeMaxDynamicSharedMemorySize, GEMM2_SMEM);
    cudaFuncSetAttribute(gemm_mma2<5>, cudaFuncAttributeMaxDynamicSharedMemorySize, GEMM2_SMEM);
    cudaFuncSetAttribute(gemm_mma2<6>, cudaFuncAttributeMaxDynamicSharedMemorySize, GEMM2_SMEM);

    convert_all_k<<<4096, 256>>>((const float4*)Wr, (const float4*)Wk,
                                 (const float4*)Wv, (const float4*)Wo,
                                 (const float4*)Wfr, (const float4*)Wfk,
                                 (const float4*)Wfv, (const float4*)head_W,
                                 (uint4*)wt);

    embed_k<<<M, 256>>>(idx, emb, x);

    dim3 gRKV(M / 128, 24);        // fused r/k/v     (384 CTAs)
    dim3 gCM (M / 128, 40);        // fused gate/kf   (640 CTAs)
    dim3 gCCg(M / 128, C / 128);   // 16 x 8 = 128 CTAs
    dim3 gCVg(M / 128, V / 128);   // 16 x 393

    for (int l = 0; l < L; l++) {
        size_t wcc = (size_t)l * C * C;
        size_t wcf = (size_t)l * C * F;
        const float* l1w = ln1_w + (size_t)l * C;
        const float* l1b = ln1_b + (size_t)l * C;
        const float* wd  = w_decay + (size_t)l * C;
        const float* ub  = u_bonus + (size_t)l * C;
        const float* l2w = ln2_w + (size_t)l * C;
        const float* l2b = ln2_b + (size_t)l * C;

        // time-mix
        layernorm_k<<<M, 256>>>(x, l1w, l1b, xnh, xnl);
        gemm_mma2<5><<<gRKV, 256, GEMM2_SMEM>>>(
            xnh, xnl, wt + O_WR + wcc, nullptr,
            r, nullptr, nullptr, k, v, C, C);
        wkv_agg_k<<<(B * CH * C) / 256, 256>>>(k, v, wd, aFkv, aFk, aBkv, aBk);
        wkv_scan_k<<<(B * C) / 256, 256>>>(wd, aFkv, aFk, aBkv, aBk,
                                           iFkv, iFk, iBkv, iBk);
        wkv_apply_k<<<(B * CH * C) / 256, 256>>>(r, k, v, wd, ub,
                                                 iFkv, iFk, iBkv, iBk,
                                                 yh, yl, sa, sb);
        gemm_mma<3><<<gCCg, GTHREADS, GEMM_SMEM>>>(
            yh, yl, wt + O_WO + wcc, x, x, nullptr, C, C);

        // channel-mix
        layernorm_k<<<M, 256>>>(x, l2w, l2b, xnh, xnl);
        gemm_mma2<6><<<gCM, 256, GEMM2_SMEM>>>(
            xnh, xnl, wt + O_WFR + wcc, wt + O_WFK + wcf,
            r, kfh, kfl, nullptr, nullptr, F, C);
        gemm_mma<4><<<gCCg, GTHREADS, GEMM_SMEM>>>(
            kfh, kfl, wt + O_WFV + wcf, x, x, r, C, F);
    }

    layernorm_k<<<M, 256>>>(x, lnout_w, lnout_b, xnh, xnl);
    gemm_mma2<0><<<gCVg, 256, GEMM2_SMEM>>>(
        xnh, xnl, wt + O_HEAD, nullptr,
        out, nullptr, nullptr, nullptr, nullptr, V, C);
}